// round 1
// baseline (speedup 1.0000x reference)
#include <cuda_runtime.h>
#include <math.h>

#define LSEQ 4096
#define DM   1024
#define BB   8
#define NF   4096          // complex FFT size (real FFT of 8192 via packing)
#define MH   4096          // half of 8192

// ---------------- device scratch (no allocations allowed) ----------------
__device__ float2 g_Kf[DM * (MH + 1)];                 // kernel spectra, 33.5 MB
__device__ float  g_g[(size_t)BB * DM * LSEQ];         // gelu output, 134 MB
__device__ float2 g_tw[NF / 2];                        // e^{-2pi i j/4096}, j=0..2047
__device__ float2 g_tw2[MH / 2 + 1];                   // e^{-2pi i k/8192}, k=0..2048

__device__ __forceinline__ float2 cmulf(float2 a, float2 b) {
    return make_float2(a.x * b.x - a.y * b.y, a.x * b.y + a.y * b.x);
}

// ---------------- twiddle tables ----------------
__global__ void init_tables_kernel() {
    int i = blockIdx.x * blockDim.x + threadIdx.x;
    if (i < NF / 2) {
        float a = (float)i / (float)(NF / 2);          // angle = pi*a = 2pi i/4096
        g_tw[i] = make_float2(cospif(a), -sinpif(a));
    }
    if (i <= MH / 2) {
        float a = (float)i / (float)MH;                // angle = 2pi i/8192
        g_tw2[i] = make_float2(cospif(a), -sinpif(a));
    }
}

// ---------------- in-place-ish Stockham FFT, N=4096 complex, smem ----------------
// Caller must __syncthreads() before calling. Result ends in s0.
__device__ __forceinline__ void fft4096_sm(float2* s0, float2* s1,
                                           const float2* tw, float dir, int tid) {
    float2* src = s0;
    float2* dst = s1;
#pragma unroll 1
    for (int pass = 0; pass < 12; pass++) {
        int s = 1 << pass;
#pragma unroll
        for (int it = 0; it < 8; it++) {
            int idx = tid + it * 256;
            int q = idx & (s - 1);
            int t = idx - q;                 // twiddle index AND j*s
            float2 c0 = src[idx];
            float2 c1 = src[idx + 2048];
            float2 w = tw[t];
            float wi = dir * w.y;
            float2 su = make_float2(c0.x + c1.x, c0.y + c1.y);
            float dx = c0.x - c1.x, dy = c0.y - c1.y;
            float2 df = make_float2(dx * w.x - dy * wi, dx * wi + dy * w.x);
            int o = 2 * idx - q;
            dst[o]     = su;
            dst[o + s] = df;
        }
        __syncthreads();
        float2* tmp = src; src = dst; dst = tmp;
    }
}

// ---------------- build kernel spectrum: interp + norm + rfft ----------------
__global__ void build_kf_kernel(const float* __restrict__ k0, const float* __restrict__ k1,
                                const float* __restrict__ k2, const float* __restrict__ k3,
                                const float* __restrict__ k4, const float* __restrict__ k5,
                                const float* __restrict__ k6) {
    extern __shared__ float2 smem[];
    float2* s0  = smem;
    float2* s1  = smem + NF;
    float2* tws = smem + 2 * NF;
    __shared__ float red[8];
    int d = blockIdx.x;
    int tid = threadIdx.x;
    float* kr = (float*)s1;                 // 4096 reals staged in s1's space

    const float* segp[7] = {k0, k1, k2, k3, k4, k5, k6};

    float ss = 0.f;
    for (int t = tid; t < LSEQ; t += 256) {
        int seg, scale, off;
        if      (t < 64)   { seg = 0; scale = 1;  off = 0;    }
        else if (t < 128)  { seg = 1; scale = 1;  off = 64;   }
        else if (t < 256)  { seg = 2; scale = 2;  off = 128;  }
        else if (t < 512)  { seg = 3; scale = 4;  off = 256;  }
        else if (t < 1024) { seg = 4; scale = 8;  off = 512;  }
        else if (t < 2048) { seg = 5; scale = 16; off = 1024; }
        else               { seg = 6; scale = 32; off = 2048; }
        int j = t - off;
        float coord = ((float)j + 0.5f) / (float)scale - 0.5f;
        coord = fminf(fmaxf(coord, 0.f), 63.f);
        int lo = (int)coord;                // coord >= 0 -> trunc == floor
        int hi = min(lo + 1, 63);
        float w = coord - (float)lo;
        const float* kp = segp[seg] + d * 64;
        float v = kp[lo] * (1.f - w) + kp[hi] * w;
        kr[t] = v;
        ss += v * v;
    }
    for (int o = 16; o > 0; o >>= 1) ss += __shfl_xor_sync(0xffffffffu, ss, o);
    if ((tid & 31) == 0) red[tid >> 5] = ss;
    __syncthreads();
    float tot = 0.f;
#pragma unroll
    for (int i = 0; i < 8; i++) tot += red[i];
    float sc = 1.0f / sqrtf(tot);

    for (int i = tid; i < NF / 2; i += 256) tws[i] = g_tw[i];
    // pack normalized reals into complex (even,odd); upper half zero (zero-pad to 8192)
    for (int n = tid; n < NF / 2; n += 256)
        s0[n] = make_float2(kr[2 * n] * sc, kr[2 * n + 1] * sc);
    for (int n = NF / 2 + tid; n < NF; n += 256) s0[n] = make_float2(0.f, 0.f);
    __syncthreads();
    fft4096_sm(s0, s1, tws, 1.0f, tid);

    // unpack packed-complex FFT -> rfft(8192) spectrum, store k=0..4096
    float2* Kf = g_Kf + (size_t)d * (MH + 1);
    for (int k = tid; k <= 2048; k += 256) {
        if (k == 0) {
            float2 Z0 = s0[0];
            Kf[0]  = make_float2(Z0.x + Z0.y, 0.f);
            Kf[MH] = make_float2(Z0.x - Z0.y, 0.f);
        } else if (k == 2048) {
            float2 Z = s0[2048];
            Kf[2048] = make_float2(Z.x, -Z.y);
        } else {
            float2 Za = s0[k], Zb = s0[NF - k];
            float2 E  = make_float2(0.5f * (Za.x + Zb.x), 0.5f * (Za.y - Zb.y));
            float2 Dm = make_float2(0.5f * (Za.x - Zb.x), 0.5f * (Za.y + Zb.y));
            float2 O  = make_float2(Dm.y, -Dm.x);        // -i * Dm
            float2 w  = g_tw2[k];
            float2 WO = cmulf(w, O);
            Kf[k]      = make_float2(E.x + WO.x, E.y + WO.y);
            Kf[MH - k] = make_float2(E.x - WO.x, -(E.y - WO.y));
        }
    }
}

// ---------------- per-row conv: rfft(u) * Kf -> irfft -> skip -> gelu ----------------
__global__ void conv_kernel(const float* __restrict__ u, const float* __restrict__ Dv) {
    extern __shared__ float2 smem[];
    float2* s0  = smem;
    float2* s1  = smem + NF;
    float2* tws = smem + 2 * NF;
    int row = blockIdx.x;                    // b*DM + d
    int d = row & (DM - 1);
    int tid = threadIdx.x;
    const float2* u2 = (const float2*)(u + (size_t)row * LSEQ);

    for (int i = tid; i < NF / 2; i += 256) tws[i] = g_tw[i];
    for (int n = tid; n < 2048; n += 256) s0[n] = u2[n];             // pack even/odd
    for (int n = 2048 + tid; n < NF; n += 256) s0[n] = make_float2(0.f, 0.f);
    __syncthreads();
    fft4096_sm(s0, s1, tws, 1.0f, tid);      // Z in s0

    // spectrum: unpack X, multiply by Kf, repack Z' for inverse. reads s0, writes s1.
    const float2* Kf = g_Kf + (size_t)d * (MH + 1);
    for (int k = tid; k <= 2048; k += 256) {
        if (k == 0) {
            float2 Z0 = s0[0];
            float X0 = Z0.x + Z0.y;
            float XM = Z0.x - Z0.y;
            float2 K0 = Kf[0], KM = Kf[MH];
            float2 Y0 = make_float2(X0 * K0.x, X0 * K0.y);
            float2 YM = make_float2(XM * KM.x, XM * KM.y);
            float2 Ep = make_float2(0.5f * (Y0.x + YM.x), 0.5f * (Y0.y - YM.y));
            float2 Op = make_float2(0.5f * (Y0.x - YM.x), 0.5f * (Y0.y + YM.y));
            s1[0] = make_float2(Ep.x - Op.y, Ep.y + Op.x);
        } else if (k == 2048) {
            float2 Z = s0[2048];
            float2 X = make_float2(Z.x, -Z.y);
            float2 Y = cmulf(X, Kf[2048]);
            s1[2048] = make_float2(Y.x, -Y.y);
        } else {
            float2 Za = s0[k], Zb = s0[NF - k];
            float2 E  = make_float2(0.5f * (Za.x + Zb.x), 0.5f * (Za.y - Zb.y));
            float2 Dm = make_float2(0.5f * (Za.x - Zb.x), 0.5f * (Za.y + Zb.y));
            float2 O  = make_float2(Dm.y, -Dm.x);
            float2 w  = g_tw2[k];
            float2 WO = cmulf(w, O);
            float2 Xa = make_float2(E.x + WO.x, E.y + WO.y);
            float2 Xb = make_float2(E.x - WO.x, -(E.y - WO.y));  // X[M-k]
            float2 Ya = cmulf(Xa, Kf[k]);
            float2 Yb = cmulf(Xb, Kf[MH - k]);
            float2 Ep = make_float2(0.5f * (Ya.x + Yb.x), 0.5f * (Ya.y - Yb.y));
            float2 Dp = make_float2(0.5f * (Ya.x - Yb.x), 0.5f * (Ya.y + Yb.y));
            float2 V  = make_float2(w.x, -w.y);                  // e^{+2pi i k/8192}
            float2 Op = cmulf(V, Dp);
            s1[k]      = make_float2(Ep.x - Op.y, Ep.y + Op.x);
            s1[NF - k] = make_float2(Ep.x + Op.y, Op.x - Ep.y);  // conj(Ep)+i*conj(Op)
        }
    }
    __syncthreads();
    fft4096_sm(s1, s0, tws, -1.0f, tid);     // inverse (conj twiddles); result in s1

    float Dd = Dv[d];
    const float inv = 1.0f / 4096.f;
    float2* gout = (float2*)(g_g + (size_t)row * LSEQ);
#pragma unroll 1
    for (int n = tid; n < 2048; n += 256) {
        float2 z = s1[n];
        float2 uu = u2[n];
        float x0 = z.x * inv + uu.x * Dd;
        float x1 = z.y * inv + uu.y * Dd;
        float g0 = 0.5f * x0 * (1.f + erff(x0 * 0.70710678118654752f));
        float g1 = 0.5f * x1 * (1.f + erff(x1 * 0.70710678118654752f));
        gout[n] = make_float2(g0, g1);
    }
}

// ---------------- TF32 tensor-core GEMM: out[b,v,l] = sum_u W[v,u] g[b,u,l] + bias[v] ----
#define BM 128
#define BN 128
#define BK 32
#define SSTR 132

__global__ void __launch_bounds__(256) gemm_kernel(const float* __restrict__ W,
                                                   const float* __restrict__ bias,
                                                   float* __restrict__ out) {
    __shared__ float Ws[BK * SSTR];          // [kk][v]
    __shared__ float Gs[BK * SSTR];          // [kk][l]
    int b  = blockIdx.z;
    int v0 = blockIdx.y * BM;
    int l0 = blockIdx.x * BN;
    int tid = threadIdx.x;
    int wid = tid >> 5, lane = tid & 31;
    int wm = wid >> 2, wn = wid & 3;         // 2x4 warp grid; warp tile 64(v) x 32(l)
    int grp = lane >> 2, qid = lane & 3;

    const float* gbase = g_g + (size_t)b * DM * LSEQ;

    float acc[4][4][4];
#pragma unroll
    for (int i = 0; i < 4; i++)
#pragma unroll
        for (int j = 0; j < 4; j++)
#pragma unroll
            for (int r = 0; r < 4; r++) acc[i][j][r] = 0.f;

    for (int u0 = 0; u0 < DM; u0 += BK) {
#pragma unroll
        for (int rep = 0; rep < 4; rep++) {          // W tile 128x32, transpose to [kk][v]
            int idx4 = rep * 256 + tid;
            int r = idx4 >> 3;
            int c4 = idx4 & 7;
            float4 wv = *(const float4*)(W + (size_t)(v0 + r) * DM + u0 + c4 * 4);
            Ws[(c4 * 4 + 0) * SSTR + r] = wv.x;
            Ws[(c4 * 4 + 1) * SSTR + r] = wv.y;
            Ws[(c4 * 4 + 2) * SSTR + r] = wv.z;
            Ws[(c4 * 4 + 3) * SSTR + r] = wv.w;
        }
#pragma unroll
        for (int rep = 0; rep < 4; rep++) {          // G tile 32x128, natural [kk][l]
            int idx4 = rep * 256 + tid;
            int r = idx4 >> 5;
            int c4 = idx4 & 31;
            float4 gv = *(const float4*)(gbase + (size_t)(u0 + r) * LSEQ + l0 + c4 * 4);
            *(float4*)(Gs + r * SSTR + c4 * 4) = gv;
        }
        __syncthreads();
#pragma unroll
        for (int ks = 0; ks < BK; ks += 8) {
            unsigned bf[4][2];
#pragma unroll
            for (int nt = 0; nt < 4; nt++) {
                int cn = wn * 32 + nt * 8 + grp;
                float f0 = Gs[(ks + qid) * SSTR + cn];
                float f1 = Gs[(ks + qid + 4) * SSTR + cn];
                asm("cvt.rna.tf32.f32 %0, %1;" : "=r"(bf[nt][0]) : "f"(f0));
                asm("cvt.rna.tf32.f32 %0, %1;" : "=r"(bf[nt][1]) : "f"(f1));
            }
#pragma unroll
            for (int mt = 0; mt < 4; mt++) {
                int rm = wm * 64 + mt * 16;
                float a0f = Ws[(ks + qid) * SSTR + rm + grp];
                float a1f = Ws[(ks + qid) * SSTR + rm + grp + 8];
                float a2f = Ws[(ks + qid + 4) * SSTR + rm + grp];
                float a3f = Ws[(ks + qid + 4) * SSTR + rm + grp + 8];
                unsigned a0, a1, a2, a3;
                asm("cvt.rna.tf32.f32 %0, %1;" : "=r"(a0) : "f"(a0f));
                asm("cvt.rna.tf32.f32 %0, %1;" : "=r"(a1) : "f"(a1f));
                asm("cvt.rna.tf32.f32 %0, %1;" : "=r"(a2) : "f"(a2f));
                asm("cvt.rna.tf32.f32 %0, %1;" : "=r"(a3) : "f"(a3f));
#pragma unroll
                for (int nt = 0; nt < 4; nt++) {
                    asm volatile(
                        "mma.sync.aligned.m16n8k8.row.col.f32.tf32.tf32.f32 "
                        "{%0,%1,%2,%3}, {%4,%5,%6,%7}, {%8,%9}, {%0,%1,%2,%3};\n"
                        : "+f"(acc[mt][nt][0]), "+f"(acc[mt][nt][1]),
                          "+f"(acc[mt][nt][2]), "+f"(acc[mt][nt][3])
                        : "r"(a0), "r"(a1), "r"(a2), "r"(a3),
                          "r"(bf[nt][0]), "r"(bf[nt][1]));
                }
            }
        }
        __syncthreads();
    }
#pragma unroll
    for (int mt = 0; mt < 4; mt++) {
        int v = v0 + wm * 64 + mt * 16 + grp;
        float bi0 = bias[v], bi1 = bias[v + 8];
#pragma unroll
        for (int nt = 0; nt < 4; nt++) {
            int l = l0 + wn * 32 + nt * 8 + qid * 2;
            float2* o0 = (float2*)(out + ((size_t)b * DM + v) * LSEQ + l);
            float2* o1 = (float2*)(out + ((size_t)b * DM + v + 8) * LSEQ + l);
            *o0 = make_float2(acc[mt][nt][0] + bi0, acc[mt][nt][1] + bi0);
            *o1 = make_float2(acc[mt][nt][2] + bi1, acc[mt][nt][3] + bi1);
        }
    }
}

// ---------------- launch ----------------
extern "C" void kernel_launch(void* const* d_in, const int* in_sizes, int n_in,
                              void* d_out, int out_size) {
    const float* u  = (const float*)d_in[0];
    const float* k0 = (const float*)d_in[1];
    const float* k1 = (const float*)d_in[2];
    const float* k2 = (const float*)d_in[3];
    const float* k3 = (const float*)d_in[4];
    const float* k4 = (const float*)d_in[5];
    const float* k5 = (const float*)d_in[6];
    const float* k6 = (const float*)d_in[7];
    const float* Dv = (const float*)d_in[8];
    const float* W  = (const float*)d_in[9];
    const float* bi = (const float*)d_in[10];
    float* out = (float*)d_out;

    const int smem_fft = (2 * NF + NF / 2) * (int)sizeof(float2);   // 81920 B
    cudaFuncSetAttribute(conv_kernel, cudaFuncAttributeMaxDynamicSharedMemorySize, smem_fft);
    cudaFuncSetAttribute(build_kf_kernel, cudaFuncAttributeMaxDynamicSharedMemorySize, smem_fft);

    init_tables_kernel<<<9, 256>>>();
    build_kf_kernel<<<DM, 256, smem_fft>>>(k0, k1, k2, k3, k4, k5, k6);
    conv_kernel<<<BB * DM, 256, smem_fft>>>(u, Dv);
    dim3 gg(LSEQ / BN, DM / BM, BB);
    gemm_kernel<<<gg, 256>>>(W, bi, out);
}

// round 3
// speedup vs baseline: 1.4915x; 1.4915x over previous
#include <cuda_runtime.h>
#include <math.h>

#define LSEQ 4096
#define DM   1024
#define BB   8
#define NF   4096          // complex FFT size (real FFT of 8192 via packing)
#define MH   4096          // half of 8192

// ---------------- device scratch (no allocations allowed) ----------------
__device__ float2   g_Kf[DM * (MH + 1)];                 // kernel spectra, 33.5 MB
__device__ unsigned g_g[(size_t)BB * DM * LSEQ];         // gelu output as TF32 bits, 134 MB
__device__ unsigned g_Wt[DM * DM];                       // W as TF32 bits, 4 MB
__device__ float2   g_tw[NF / 2];                        // e^{-2pi i j/4096}, j=0..2047
__device__ float2   g_tw2[MH / 2 + 1];                   // e^{-2pi i k/8192}, k=0..2048

__device__ __forceinline__ float2 cmulf(float2 a, float2 b) {
    return make_float2(a.x * b.x - a.y * b.y, a.x * b.y + a.y * b.x);
}
__device__ __forceinline__ unsigned f2tf32(float f) {
    unsigned r;
    asm("cvt.rna.tf32.f32 %0, %1;" : "=r"(r) : "f"(f));
    return r;
}

// ---------------- twiddle tables ----------------
__global__ void init_tables_kernel() {
    int i = blockIdx.x * blockDim.x + threadIdx.x;
    if (i < NF / 2) {
        float a = (float)i / (float)(NF / 2);
        g_tw[i] = make_float2(cospif(a), -sinpif(a));
    }
    if (i <= MH / 2) {
        float a = (float)i / (float)MH;
        g_tw2[i] = make_float2(cospif(a), -sinpif(a));
    }
}

__global__ void cvt_w_kernel(const float* __restrict__ W) {
    int i = blockIdx.x * blockDim.x + threadIdx.x;
    if (i < DM * DM) g_Wt[i] = f2tf32(W[i]);
}

// ---------------- radix-4 Stockham FFT, N=4096 complex, smem ----------------
// Exact fusion of consecutive radix-2 Stockham pass pairs; 6 passes total.
// Caller must __syncthreads() before calling. Result ends in s0.
__device__ __forceinline__ void fft4096_r4(float2* s0, float2* s1,
                                           const float2* tw, float dir, int tid) {
    float2* src = s0;
    float2* dst = s1;
#pragma unroll
    for (int pass = 0; pass < 6; pass++) {
        int s = 1 << (2 * pass);
#pragma unroll
        for (int it = 0; it < 4; it++) {
            int j = tid + it * 256;
            int q = j & (s - 1);
            int as = j - q;                    // a*s
            float2 c0 = src[j];
            float2 c1 = src[j + 1024];
            float2 c2 = src[j + 2048];
            float2 c3 = src[j + 3072];
            float2 wa = tw[as];
            float way = dir * wa.y;
            float2 wc = tw[2 * as];
            float wcy = dir * wc.y;
            float2 S02 = make_float2(c0.x + c2.x, c0.y + c2.y);
            float dx = c0.x - c2.x, dy = c0.y - c2.y;
            float2 D02 = make_float2(dx * wa.x - dy * way, dx * way + dy * wa.x);
            float2 S13 = make_float2(c1.x + c3.x, c1.y + c3.y);
            float ex = c1.x - c3.x, ey = c1.y - c3.y;
            float2 T = make_float2(ex * wa.x - ey * way, ex * way + ey * wa.x);
            float2 D13 = make_float2(dir * T.y, -dir * T.x);   // (-i*dir) * T
            float2 o0 = make_float2(S02.x + S13.x, S02.y + S13.y);
            float2 o1 = make_float2(D02.x + D13.x, D02.y + D13.y);
            float mx = S02.x - S13.x, my = S02.y - S13.y;
            float2 o2 = make_float2(mx * wc.x - my * wcy, mx * wcy + my * wc.x);
            float nx = D02.x - D13.x, ny = D02.y - D13.y;
            float2 o3 = make_float2(nx * wc.x - ny * wcy, nx * wcy + ny * wc.x);
            int ob = 4 * as + q;
            if (s == 1) {                      // ob = 4j: contiguous, vectorize
                float4* d4 = (float4*)(dst + ob);
                d4[0] = make_float4(o0.x, o0.y, o1.x, o1.y);
                d4[1] = make_float4(o2.x, o2.y, o3.x, o3.y);
            } else {
                dst[ob]         = o0;
                dst[ob + s]     = o1;
                dst[ob + 2 * s] = o2;
                dst[ob + 3 * s] = o3;
            }
        }
        __syncthreads();
        float2* tmp = src; src = dst; dst = tmp;
    }
}

// ---------------- build kernel spectrum: interp + norm + rfft ----------------
__global__ void build_kf_kernel(const float* __restrict__ k0, const float* __restrict__ k1,
                                const float* __restrict__ k2, const float* __restrict__ k3,
                                const float* __restrict__ k4, const float* __restrict__ k5,
                                const float* __restrict__ k6) {
    extern __shared__ float2 smem[];
    float2* s0  = smem;
    float2* s1  = smem + NF;
    float2* tws = smem + 2 * NF;
    __shared__ float red[8];
    int d = blockIdx.x;
    int tid = threadIdx.x;
    float* kr = (float*)s1;

    const float* segp[7] = {k0, k1, k2, k3, k4, k5, k6};

    float ss = 0.f;
    for (int t = tid; t < LSEQ; t += 256) {
        int seg, scale, off;
        if      (t < 64)   { seg = 0; scale = 1;  off = 0;    }
        else if (t < 128)  { seg = 1; scale = 1;  off = 64;   }
        else if (t < 256)  { seg = 2; scale = 2;  off = 128;  }
        else if (t < 512)  { seg = 3; scale = 4;  off = 256;  }
        else if (t < 1024) { seg = 4; scale = 8;  off = 512;  }
        else if (t < 2048) { seg = 5; scale = 16; off = 1024; }
        else               { seg = 6; scale = 32; off = 2048; }
        int j = t - off;
        float coord = ((float)j + 0.5f) / (float)scale - 0.5f;
        coord = fminf(fmaxf(coord, 0.f), 63.f);
        int lo = (int)coord;
        int hi = min(lo + 1, 63);
        float w = coord - (float)lo;
        const float* kp = segp[seg] + d * 64;
        float v = kp[lo] * (1.f - w) + kp[hi] * w;
        kr[t] = v;
        ss += v * v;
    }
    for (int o = 16; o > 0; o >>= 1) ss += __shfl_xor_sync(0xffffffffu, ss, o);
    if ((tid & 31) == 0) red[tid >> 5] = ss;
    __syncthreads();
    float tot = 0.f;
#pragma unroll
    for (int i = 0; i < 8; i++) tot += red[i];
    float sc = 1.0f / sqrtf(tot);

    for (int i = tid; i < NF / 2; i += 256) tws[i] = g_tw[i];
    for (int n = tid; n < NF / 2; n += 256)
        s0[n] = make_float2(kr[2 * n] * sc, kr[2 * n + 1] * sc);
    for (int n = NF / 2 + tid; n < NF; n += 256) s0[n] = make_float2(0.f, 0.f);
    __syncthreads();
    fft4096_r4(s0, s1, tws, 1.0f, tid);

    float2* Kf = g_Kf + (size_t)d * (MH + 1);
    for (int k = tid; k <= 2048; k += 256) {
        if (k == 0) {
            float2 Z0 = s0[0];
            Kf[0]  = make_float2(Z0.x + Z0.y, 0.f);
            Kf[MH] = make_float2(Z0.x - Z0.y, 0.f);
        } else if (k == 2048) {
            float2 Z = s0[2048];
            Kf[2048] = make_float2(Z.x, -Z.y);
        } else {
            float2 Za = s0[k], Zb = s0[NF - k];
            float2 E  = make_float2(0.5f * (Za.x + Zb.x), 0.5f * (Za.y - Zb.y));
            float2 Dm = make_float2(0.5f * (Za.x - Zb.x), 0.5f * (Za.y + Zb.y));
            float2 O  = make_float2(Dm.y, -Dm.x);
            float2 w  = g_tw2[k];
            float2 WO = cmulf(w, O);
            Kf[k]      = make_float2(E.x + WO.x, E.y + WO.y);
            Kf[MH - k] = make_float2(E.x - WO.x, -(E.y - WO.y));
        }
    }
}

// ---------------- per-row conv: rfft(u) * Kf -> irfft -> skip -> gelu -> tf32 ----------------
__global__ void conv_kernel(const float* __restrict__ u, const float* __restrict__ Dv) {
    extern __shared__ float2 smem[];
    float2* s0  = smem;
    float2* s1  = smem + NF;
    float2* tws = smem + 2 * NF;
    int row = blockIdx.x;                    // b*DM + d
    int d = row & (DM - 1);
    int tid = threadIdx.x;
    const float2* u2 = (const float2*)(u + (size_t)row * LSEQ);

    for (int i = tid; i < NF / 2; i += 256) tws[i] = g_tw[i];
    for (int n = tid; n < 2048; n += 256) s0[n] = u2[n];
    for (int n = 2048 + tid; n < NF; n += 256) s0[n] = make_float2(0.f, 0.f);
    __syncthreads();
    fft4096_r4(s0, s1, tws, 1.0f, tid);      // Z in s0

    const float2* Kf = g_Kf + (size_t)d * (MH + 1);
    for (int k = tid; k <= 2048; k += 256) {
        if (k == 0) {
            float2 Z0 = s0[0];
            float X0 = Z0.x + Z0.y;
            float XM = Z0.x - Z0.y;
            float2 K0 = Kf[0], KM = Kf[MH];
            float2 Y0 = make_float2(X0 * K0.x, X0 * K0.y);
            float2 YM = make_float2(XM * KM.x, XM * KM.y);
            float2 Ep = make_float2(0.5f * (Y0.x + YM.x), 0.5f * (Y0.y - YM.y));
            float2 Op = make_float2(0.5f * (Y0.x - YM.x), 0.5f * (Y0.y + YM.y));
            s1[0] = make_float2(Ep.x - Op.y, Ep.y + Op.x);
        } else if (k == 2048) {
            float2 Z = s0[2048];
            float2 X = make_float2(Z.x, -Z.y);
            float2 Y = cmulf(X, Kf[2048]);
            s1[2048] = make_float2(Y.x, -Y.y);
        } else {
            float2 Za = s0[k], Zb = s0[NF - k];
            float2 E  = make_float2(0.5f * (Za.x + Zb.x), 0.5f * (Za.y - Zb.y));
            float2 Dm = make_float2(0.5f * (Za.x - Zb.x), 0.5f * (Za.y + Zb.y));
            float2 O  = make_float2(Dm.y, -Dm.x);
            float2 w  = g_tw2[k];
            float2 WO = cmulf(w, O);
            float2 Xa = make_float2(E.x + WO.x, E.y + WO.y);
            float2 Xb = make_float2(E.x - WO.x, -(E.y - WO.y));
            float2 Ya = cmulf(Xa, Kf[k]);
            float2 Yb = cmulf(Xb, Kf[MH - k]);
            float2 Ep = make_float2(0.5f * (Ya.x + Yb.x), 0.5f * (Ya.y - Yb.y));
            float2 Dp = make_float2(0.5f * (Ya.x - Yb.x), 0.5f * (Ya.y + Yb.y));
            float2 V  = make_float2(w.x, -w.y);
            float2 Op = cmulf(V, Dp);
            s1[k]      = make_float2(Ep.x - Op.y, Ep.y + Op.x);
            s1[NF - k] = make_float2(Ep.x + Op.y, Op.x - Ep.y);
        }
    }
    __syncthreads();
    fft4096_r4(s1, s0, tws, -1.0f, tid);     // inverse; result in s1

    float Dd = Dv[d];
    const float inv = 1.0f / 4096.f;
    uint2* gout = (uint2*)(g_g + (size_t)row * LSEQ);
#pragma unroll 1
    for (int n = tid; n < 2048; n += 256) {
        float2 z = s1[n];
        float2 uu = u2[n];
        float x0 = z.x * inv + uu.x * Dd;
        float x1 = z.y * inv + uu.y * Dd;
        float g0 = 0.5f * x0 * (1.f + erff(x0 * 0.70710678118654752f));
        float g1 = 0.5f * x1 * (1.f + erff(x1 * 0.70710678118654752f));
        gout[n] = make_uint2(f2tf32(g0), f2tf32(g1));
    }
}

// ---------------- TF32 tensor-core GEMM: out[b,v,l] = sum_u W[v,u] g[b,u,l] + bias[v] ----
#define BM 128
#define BN 128
#define BK 32
#define SA 36     // As row stride (floats): [v][kk]
#define SB 136    // Bs row stride (floats): [kk][l]
#define A_SZ (BM * SA)
#define B_SZ (BK * SB)

__device__ __forceinline__ void cpa16(void* s, const void* g) {
    unsigned sa = (unsigned)__cvta_generic_to_shared(s);
    asm volatile("cp.async.cg.shared.global [%0], [%1], 16;\n" :: "r"(sa), "l"(g));
}
__device__ __forceinline__ void ldsm4(unsigned& r0, unsigned& r1, unsigned& r2, unsigned& r3,
                                      const void* p) {
    unsigned a = (unsigned)__cvta_generic_to_shared(p);
    asm volatile("ldmatrix.sync.aligned.m8n8.x4.shared.b16 {%0,%1,%2,%3}, [%4];\n"
                 : "=r"(r0), "=r"(r1), "=r"(r2), "=r"(r3) : "r"(a));
}

__global__ void __launch_bounds__(256) gemm_kernel(const float* __restrict__ bias,
                                                   float* __restrict__ out) {
    extern __shared__ unsigned gsm[];
    unsigned* As[2] = {gsm, gsm + A_SZ + B_SZ};
    unsigned* Bs[2] = {gsm + A_SZ, gsm + 2 * A_SZ + B_SZ};

    int b  = blockIdx.z;
    int v0 = blockIdx.y * BM;
    int l0 = blockIdx.x * BN;
    int tid = threadIdx.x;
    int wid = tid >> 5, lane = tid & 31;
    int wm = wid >> 2, wn = wid & 3;         // 2x4 warp grid; warp tile 64(v) x 32(l)
    int grp = lane >> 2, qid = lane & 3;

    const unsigned* gbase = g_g + (size_t)b * DM * LSEQ;

    float acc[4][4][4];
#pragma unroll
    for (int i = 0; i < 4; i++)
#pragma unroll
        for (int j = 0; j < 4; j++)
#pragma unroll
            for (int r = 0; r < 4; r++) acc[i][j][r] = 0.f;

    // ---- async staging of one BK-slab into stage st ----
    auto stage_load = [&](int st, int u0) {
#pragma unroll
        for (int rep = 0; rep < 4; rep++) {          // A: W tile 128x32 (natural [v][kk])
            int idx4 = rep * 256 + tid;
            int r = idx4 >> 3, c = idx4 & 7;
            cpa16(As[st] + r * SA + c * 4, g_Wt + (size_t)(v0 + r) * DM + u0 + c * 4);
        }
#pragma unroll
        for (int rep = 0; rep < 4; rep++) {          // B: g tile 32x128 ([kk][l])
            int idx4 = rep * 256 + tid;
            int r = idx4 >> 5, c = idx4 & 31;
            cpa16(Bs[st] + r * SB + c * 4, gbase + (size_t)(u0 + r) * LSEQ + l0 + c * 4);
        }
        asm volatile("cp.async.commit_group;\n");
    };

    stage_load(0, 0);

    const int NIT = DM / BK;                 // 32
    for (int it = 0; it < NIT; it++) {
        if (it + 1 < NIT) {
            stage_load((it + 1) & 1, (it + 1) * BK);
            asm volatile("cp.async.wait_group 1;\n");
        } else {
            asm volatile("cp.async.wait_group 0;\n");
        }
        __syncthreads();
        const unsigned* A = As[it & 1];
        const unsigned* Bsm = Bs[it & 1];
#pragma unroll
        for (int ks = 0; ks < BK; ks += 8) {
            unsigned bf[4][2];
#pragma unroll
            for (int nt = 0; nt < 4; nt++) {
                int cn = wn * 32 + nt * 8 + grp;
                bf[nt][0] = Bsm[(ks + qid) * SB + cn];
                bf[nt][1] = Bsm[(ks + qid + 4) * SB + cn];
            }
#pragma unroll
            for (int mt = 0; mt < 4; mt++) {
                int rowa = wm * 64 + mt * 16 + (lane & 15);
                int cola = ks + ((lane & 16) ? 4 : 0);
                unsigned a0, a1, a2, a3;
                ldsm4(a0, a1, a2, a3, A + rowa * SA + cola);
#pragma unroll
                for (int nt = 0; nt < 4; nt++) {
                    asm volatile(
                        "mma.sync.aligned.m16n8k8.row.col.f32.tf32.tf32.f32 "
                        "{%0,%1,%2,%3}, {%4,%5,%6,%7}, {%8,%9}, {%0,%1,%2,%3};\n"
                        : "+f"(acc[mt][nt][0]), "+f"(acc[mt][nt][1]),
                          "+f"(acc[mt][nt][2]), "+f"(acc[mt][nt][3])
                        : "r"(a0), "r"(a1), "r"(a2), "r"(a3),
                          "r"(bf[nt][0]), "r"(bf[nt][1]));
                }
            }
        }
        __syncthreads();
    }
#pragma unroll
    for (int mt = 0; mt < 4; mt++) {
        int v = v0 + wm * 64 + mt * 16 + grp;
        float bi0 = bias[v], bi1 = bias[v + 8];
#pragma unroll
        for (int nt = 0; nt < 4; nt++) {
            int l = l0 + wn * 32 + nt * 8 + qid * 2;
            float2* o0 = (float2*)(out + ((size_t)b * DM + v) * LSEQ + l);
            float2* o1 = (float2*)(out + ((size_t)b * DM + v + 8) * LSEQ + l);
            *o0 = make_float2(acc[mt][nt][0] + bi0, acc[mt][nt][1] + bi0);
            *o1 = make_float2(acc[mt][nt][2] + bi1, acc[mt][nt][3] + bi1);
        }
    }
}

// ---------------- launch ----------------
extern "C" void kernel_launch(void* const* d_in, const int* in_sizes, int n_in,
                              void* d_out, int out_size) {
    const float* u  = (const float*)d_in[0];
    const float* k0 = (const float*)d_in[1];
    const float* k1 = (const float*)d_in[2];
    const float* k2 = (const float*)d_in[3];
    const float* k3 = (const float*)d_in[4];
    const float* k4 = (const float*)d_in[5];
    const float* k5 = (const float*)d_in[6];
    const float* k6 = (const float*)d_in[7];
    const float* Dv = (const float*)d_in[8];
    const float* W  = (const float*)d_in[9];
    const float* bi = (const float*)d_in[10];
    float* out = (float*)d_out;

    const int smem_fft = (2 * NF + NF / 2) * (int)sizeof(float2);        // 81920 B
    const int smem_gemm = 2 * (A_SZ + B_SZ) * (int)sizeof(unsigned);     // 71680 B
    cudaFuncSetAttribute(conv_kernel, cudaFuncAttributeMaxDynamicSharedMemorySize, smem_fft);
    cudaFuncSetAttribute(build_kf_kernel, cudaFuncAttributeMaxDynamicSharedMemorySize, smem_fft);
    cudaFuncSetAttribute(gemm_kernel, cudaFuncAttributeMaxDynamicSharedMemorySize, smem_gemm);

    init_tables_kernel<<<9, 256>>>();
    cvt_w_kernel<<<DM * DM / 256, 256>>>(W);
    build_kf_kernel<<<DM, 256, smem_fft>>>(k0, k1, k2, k3, k4, k5, k6);
    conv_kernel<<<BB * DM, 256, smem_fft>>>(u, Dv);
    dim3 gg(LSEQ / BN, DM / BM, BB);
    gemm_kernel<<<gg, 256, smem_gemm>>>(bi, out);
}

// round 4
// speedup vs baseline: 1.8567x; 1.2448x over previous
#include <cuda_runtime.h>
#include <math.h>

#define LSEQ 4096
#define DM   1024
#define BB   8
#define NF   4096          // complex FFT size (real FFT of 8192 via packing)
#define MH   4096          // half of 8192
#define S1PAD 4352         // padded second buffer: 17 * 256

// padded index map for buffer s1 (avoids 128B-stride bank conflicts)
#define PHI(i) ((((i) >> 4) * 17) + ((i) & 15))

// ---------------- device scratch (no allocations allowed) ----------------
__device__ float2   g_Kf[DM * (MH + 1)];                 // kernel spectra (pre-scaled by 1/4096)
__device__ unsigned g_g[(size_t)BB * DM * LSEQ];         // gelu output as TF32 bits
__device__ unsigned g_Wt[DM * DM];                       // W as TF32 bits
__device__ float2   g_tw[NF / 2];                        // e^{-2pi i j/4096}
__device__ float2   g_tw2[MH / 2 + 1];                   // e^{-2pi i k/8192}

__device__ __forceinline__ float2 cmulf(float2 a, float2 b) {
    return make_float2(a.x * b.x - a.y * b.y, a.x * b.y + a.y * b.x);
}
__device__ __forceinline__ unsigned f2tf32(float f) {
    unsigned r;
    asm("cvt.rna.tf32.f32 %0, %1;" : "=r"(r) : "f"(f));
    return r;
}

// ---------------- twiddle tables ----------------
__global__ void init_tables_kernel() {
    int i = blockIdx.x * blockDim.x + threadIdx.x;
    if (i < NF / 2) {
        float a = (float)i / (float)(NF / 2);
        g_tw[i] = make_float2(cospif(a), -sinpif(a));
    }
    if (i <= MH / 2) {
        float a = (float)i / (float)MH;
        g_tw2[i] = make_float2(cospif(a), -sinpif(a));
    }
}

__global__ void cvt_w_kernel(const float* __restrict__ W) {
    int i = blockIdx.x * blockDim.x + threadIdx.x;
    if (i < DM * DM) g_Wt[i] = f2tf32(W[i]);
}

// ---------------- 16-point DFT in registers (two radix-4 stages) ----------------
// X[m] = sum_r c[r] * w16^{r*m},  w16 = e^{-2*pi*i*DIR/16}.  HZ: c[8..15]==0.
template<int DIR, bool HZ>
__device__ __forceinline__ void dft16(float2* c) {
    const float d  = (float)DIR;
    const float C1 = 0.92387953251128674f;
    const float Sn = 0.38268343236508978f;
    const float HF = 0.70710678118654752f;
    float2 t[16];
#pragma unroll
    for (int r1 = 0; r1 < 4; r1++) {
        float2 a = c[r1], b = c[r1 + 4];
        if (HZ) {
            t[r1 * 4 + 0] = make_float2(a.x + b.x, a.y + b.y);
            t[r1 * 4 + 2] = make_float2(a.x - b.x, a.y - b.y);
            t[r1 * 4 + 1] = make_float2(a.x + d * b.y, a.y - d * b.x);
            t[r1 * 4 + 3] = make_float2(a.x - d * b.y, a.y + d * b.x);
        } else {
            float2 e = c[r1 + 8], f = c[r1 + 12];
            float2 t0 = make_float2(a.x + e.x, a.y + e.y);
            float2 t1 = make_float2(a.x - e.x, a.y - e.y);
            float2 t2 = make_float2(b.x + f.x, b.y + f.y);
            float2 t3 = make_float2(b.x - f.x, b.y - f.y);
            t[r1 * 4 + 0] = make_float2(t0.x + t2.x, t0.y + t2.y);
            t[r1 * 4 + 2] = make_float2(t0.x - t2.x, t0.y - t2.y);
            t[r1 * 4 + 1] = make_float2(t1.x + d * t3.y, t1.y - d * t3.x);
            t[r1 * 4 + 3] = make_float2(t1.x - d * t3.y, t1.y + d * t3.x);
        }
    }
    // inter-stage twiddles w16^{r1*m2}
    const float2 e1 = make_float2(C1,  -d * Sn);
    const float2 e2 = make_float2(HF,  -d * HF);
    const float2 e3 = make_float2(Sn,  -d * C1);
    const float2 e6 = make_float2(-HF, -d * HF);
    const float2 e9 = make_float2(-C1,  d * Sn);
    t[5]  = cmulf(t[5],  e1);
    t[6]  = cmulf(t[6],  e2);
    t[7]  = cmulf(t[7],  e3);
    t[9]  = cmulf(t[9],  e2);
    t[10] = make_float2(d * t[10].y, -d * t[10].x);   // * w16^4 = -i*d
    t[11] = cmulf(t[11], e6);
    t[13] = cmulf(t[13], e3);
    t[14] = cmulf(t[14], e6);
    t[15] = cmulf(t[15], e9);
#pragma unroll
    for (int m2 = 0; m2 < 4; m2++) {
        float2 a = t[m2], b = t[4 + m2], e = t[8 + m2], f = t[12 + m2];
        float2 t0 = make_float2(a.x + e.x, a.y + e.y);
        float2 t1 = make_float2(a.x - e.x, a.y - e.y);
        float2 t2 = make_float2(b.x + f.x, b.y + f.y);
        float2 t3 = make_float2(b.x - f.x, b.y - f.y);
        c[m2]      = make_float2(t0.x + t2.x, t0.y + t2.y);
        c[m2 + 8]  = make_float2(t0.x - t2.x, t0.y - t2.y);
        c[m2 + 4]  = make_float2(t1.x + d * t3.y, t1.y - d * t3.x);
        c[m2 + 12] = make_float2(t1.x - d * t3.y, t1.y + d * t3.x);
    }
}

// ---------------- radix-16 Stockham FFT, N=4096, 3 passes ----------------
// Input in s0 (plain layout). Output in s1 (padded layout via PHI).
// Caller must __syncthreads() before calling. Syncs after each pass.
template<int DIR, bool HZ>
__device__ __forceinline__ void fft4096_r16(float2* s0, float2* s1, int tid) {
    float2 c[16];
    // pass 0: s = 1. read s0 stride 256, write s1 contiguous-per-thread (padded)
    {
        int j = tid;
#pragma unroll
        for (int m = 0; m < (HZ ? 8 : 16); m++) c[m] = s0[j + 256 * m];
        dft16<DIR, HZ>(c);
        float2 w1 = g_tw[j];
        if (DIR < 0) w1.y = -w1.y;
        float2* dst = s1 + 17 * j;
        dst[0] = c[0];
        float2 w = w1;
#pragma unroll
        for (int m = 1; m < 16; m++) {
            dst[m] = cmulf(w, c[m]);
            w = cmulf(w, w1);
        }
    }
    __syncthreads();
    // pass 1: s = 16. read s1 (padded), write s0 plain
    {
        int j = tid, q = j & 15, as = j & ~15;
#pragma unroll
        for (int m = 0; m < 16; m++) c[m] = s1[PHI(j + 256 * m)];
        dft16<DIR, false>(c);
        float2 w1 = g_tw[as];
        if (DIR < 0) w1.y = -w1.y;
        int ob = 16 * as + q;
        s0[ob] = c[0];
        float2 w = w1;
#pragma unroll
        for (int m = 1; m < 16; m++) {
            s0[ob + 16 * m] = cmulf(w, c[m]);
            w = cmulf(w, w1);
        }
    }
    __syncthreads();
    // pass 2: s = 256, twiddles are all 1. read s0, write s1 (padded)
    {
        int j = tid;
#pragma unroll
        for (int m = 0; m < 16; m++) c[m] = s0[j + 256 * m];
        dft16<DIR, false>(c);
#pragma unroll
        for (int m = 0; m < 16; m++) s1[PHI(j + 256 * m)] = c[m];
    }
    __syncthreads();
}

// ---------------- build kernel spectrum: interp + norm + rfft ----------------
__global__ void build_kf_kernel(const float* __restrict__ k0, const float* __restrict__ k1,
                                const float* __restrict__ k2, const float* __restrict__ k3,
                                const float* __restrict__ k4, const float* __restrict__ k5,
                                const float* __restrict__ k6) {
    extern __shared__ float2 smem[];
    float2* s0 = smem;               // 4096, plain
    float2* s1 = smem + NF;          // 4352, padded
    __shared__ float red[8];
    int d = blockIdx.x;
    int tid = threadIdx.x;
    float* kr = (float*)s1;          // stage 4096 reals in s1's space (pre-FFT)

    const float* segp[7] = {k0, k1, k2, k3, k4, k5, k6};

    float ss = 0.f;
    for (int t = tid; t < LSEQ; t += 256) {
        int seg, scale, off;
        if      (t < 64)   { seg = 0; scale = 1;  off = 0;    }
        else if (t < 128)  { seg = 1; scale = 1;  off = 64;   }
        else if (t < 256)  { seg = 2; scale = 2;  off = 128;  }
        else if (t < 512)  { seg = 3; scale = 4;  off = 256;  }
        else if (t < 1024) { seg = 4; scale = 8;  off = 512;  }
        else if (t < 2048) { seg = 5; scale = 16; off = 1024; }
        else               { seg = 6; scale = 32; off = 2048; }
        int j = t - off;
        float coord = ((float)j + 0.5f) / (float)scale - 0.5f;
        coord = fminf(fmaxf(coord, 0.f), 63.f);
        int lo = (int)coord;
        int hi = min(lo + 1, 63);
        float w = coord - (float)lo;
        const float* kp = segp[seg] + d * 64;
        float v = kp[lo] * (1.f - w) + kp[hi] * w;
        kr[t] = v;
        ss += v * v;
    }
    for (int o = 16; o > 0; o >>= 1) ss += __shfl_xor_sync(0xffffffffu, ss, o);
    if ((tid & 31) == 0) red[tid >> 5] = ss;
    __syncthreads();
    float tot = 0.f;
#pragma unroll
    for (int i = 0; i < 8; i++) tot += red[i];
    float sc = 1.0f / sqrtf(tot);

    // pack normalized reals into complex (even,odd); upper half implicitly zero (HZ fft)
    for (int n = tid; n < NF / 2; n += 256)
        s0[n] = make_float2(kr[2 * n] * sc, kr[2 * n + 1] * sc);
    __syncthreads();
    fft4096_r16<1, true>(s0, s1, tid);       // result in s1 (padded)

    // unpack packed-complex FFT -> rfft(8192) spectrum; fold 1/4096 inverse scale
    const float INV = 1.0f / 4096.0f;
    float2* Kf = g_Kf + (size_t)d * (MH + 1);
    for (int k = tid; k <= 2048; k += 256) {
        if (k == 0) {
            float2 Z0 = s1[PHI(0)];
            Kf[0]  = make_float2((Z0.x + Z0.y) * INV, 0.f);
            Kf[MH] = make_float2((Z0.x - Z0.y) * INV, 0.f);
        } else if (k == 2048) {
            float2 Z = s1[PHI(2048)];
            Kf[2048] = make_float2(Z.x * INV, -Z.y * INV);
        } else {
            float2 Za = s1[PHI(k)], Zb = s1[PHI(NF - k)];
            float2 E  = make_float2(0.5f * (Za.x + Zb.x), 0.5f * (Za.y - Zb.y));
            float2 Dm = make_float2(0.5f * (Za.x - Zb.x), 0.5f * (Za.y + Zb.y));
            float2 O  = make_float2(Dm.y, -Dm.x);
            float2 w  = g_tw2[k];
            float2 WO = cmulf(w, O);
            Kf[k]      = make_float2((E.x + WO.x) * INV, (E.y + WO.y) * INV);
            Kf[MH - k] = make_float2((E.x - WO.x) * INV, -(E.y - WO.y) * INV);
        }
    }
}

// ---------------- per-row conv: rfft(u) * Kf -> irfft -> skip -> gelu -> tf32 ----------------
__global__ void conv_kernel(const float* __restrict__ u, const float* __restrict__ Dv) {
    extern __shared__ float2 smem[];
    float2* s0 = smem;               // 4096, plain
    float2* s1 = smem + NF;          // 4352, padded
    int row = blockIdx.x;            // b*DM + d
    int d = row & (DM - 1);
    int tid = threadIdx.x;
    const float2* u2 = (const float2*)(u + (size_t)row * LSEQ);

    for (int n = tid; n < 2048; n += 256) s0[n] = u2[n];   // pack even/odd; upper half HZ
    __syncthreads();
    fft4096_r16<1, true>(s0, s1, tid);       // Z in s1 (padded)

    // spectral: unpack X, multiply by Kf, repack Z' for inverse. reads s1, writes s0.
    const float2* Kf = g_Kf + (size_t)d * (MH + 1);
    for (int k = tid; k <= 2048; k += 256) {
        if (k == 0) {
            float2 Z0 = s1[PHI(0)];
            float X0 = Z0.x + Z0.y;
            float XM = Z0.x - Z0.y;
            float2 K0 = Kf[0], KM = Kf[MH];
            float2 Y0 = make_float2(X0 * K0.x, X0 * K0.y);
            float2 YM = make_float2(XM * KM.x, XM * KM.y);
            float2 Ep = make_float2(0.5f * (Y0.x + YM.x), 0.5f * (Y0.y - YM.y));
            float2 Op = make_float2(0.5f * (Y0.x - YM.x), 0.5f * (Y0.y + YM.y));
            s0[0] = make_float2(Ep.x - Op.y, Ep.y + Op.x);
        } else if (k == 2048) {
            float2 Z = s1[PHI(2048)];
            float2 X = make_float2(Z.x, -Z.y);
            float2 Y = cmulf(X, Kf[2048]);
            s0[2048] = make_float2(Y.x, -Y.y);
        } else {
            float2 Za = s1[PHI(k)], Zb = s1[PHI(NF - k)];
            float2 E  = make_float2(0.5f * (Za.x + Zb.x), 0.5f * (Za.y - Zb.y));
            float2 Dm = make_float2(0.5f * (Za.x - Zb.x), 0.5f * (Za.y + Zb.y));
            float2 O  = make_float2(Dm.y, -Dm.x);
            float2 w  = g_tw2[k];
            float2 WO = cmulf(w, O);
            float2 Xa = make_float2(E.x + WO.x, E.y + WO.y);
            float2 Xb = make_float2(E.x - WO.x, -(E.y - WO.y));
            float2 Ya = cmulf(Xa, Kf[k]);
            float2 Yb = cmulf(Xb, Kf[MH - k]);
            float2 Ep = make_float2(0.5f * (Ya.x + Yb.x), 0.5f * (Ya.y - Yb.y));
            float2 Dp = make_float2(0.5f * (Ya.x - Yb.x), 0.5f * (Ya.y + Yb.y));
            float2 V  = make_float2(w.x, -w.y);
            float2 Op = cmulf(V, Dp);
            s0[k]      = make_float2(Ep.x - Op.y, Ep.y + Op.x);
            s0[NF - k] = make_float2(Ep.x + Op.y, Op.x - Ep.y);
        }
    }
    __syncthreads();
    fft4096_r16<-1, false>(s0, s1, tid);     // inverse; result in s1 (padded)

    float Dd = Dv[d];
    uint2* gout = (uint2*)(g_g + (size_t)row * LSEQ);
#pragma unroll 1
    for (int n = tid; n < 2048; n += 256) {
        float2 z = s1[PHI(n)];               // 1/4096 already folded into Kf
        float2 uu = u2[n];
        float x0 = z.x + uu.x * Dd;
        float x1 = z.y + uu.y * Dd;
        float g0 = 0.5f * x0 * (1.f + erff(x0 * 0.70710678118654752f));
        float g1 = 0.5f * x1 * (1.f + erff(x1 * 0.70710678118654752f));
        gout[n] = make_uint2(f2tf32(g0), f2tf32(g1));
    }
}

// ---------------- TF32 tensor-core GEMM: out[b,v,l] = sum_u W[v,u] g[b,u,l] + bias[v] ----
#define BM 128
#define BN 128
#define BK 32
#define SA 36     // As row stride (floats): [v][kk]
#define SB 136    // Bs row stride (floats): [kk][l]
#define A_SZ (BM * SA)
#define B_SZ (BK * SB)

__device__ __forceinline__ void cpa16(void* s, const void* g) {
    unsigned sa = (unsigned)__cvta_generic_to_shared(s);
    asm volatile("cp.async.cg.shared.global [%0], [%1], 16;\n" :: "r"(sa), "l"(g));
}
__device__ __forceinline__ void ldsm4(unsigned& r0, unsigned& r1, unsigned& r2, unsigned& r3,
                                      const void* p) {
    unsigned a = (unsigned)__cvta_generic_to_shared(p);
    asm volatile("ldmatrix.sync.aligned.m8n8.x4.shared.b16 {%0,%1,%2,%3}, [%4];\n"
                 : "=r"(r0), "=r"(r1), "=r"(r2), "=r"(r3) : "r"(a));
}

__global__ void __launch_bounds__(256) gemm_kernel(const float* __restrict__ bias,
                                                   float* __restrict__ out) {
    extern __shared__ unsigned gsm[];
    unsigned* As[2] = {gsm, gsm + A_SZ + B_SZ};
    unsigned* Bs[2] = {gsm + A_SZ, gsm + 2 * A_SZ + B_SZ};

    int b  = blockIdx.z;
    int v0 = blockIdx.y * BM;
    int l0 = blockIdx.x * BN;
    int tid = threadIdx.x;
    int wid = tid >> 5, lane = tid & 31;
    int wm = wid >> 2, wn = wid & 3;         // 2x4 warp grid; warp tile 64(v) x 32(l)
    int grp = lane >> 2, qid = lane & 3;

    const unsigned* gbase = g_g + (size_t)b * DM * LSEQ;

    float acc[4][4][4];
#pragma unroll
    for (int i = 0; i < 4; i++)
#pragma unroll
        for (int j = 0; j < 4; j++)
#pragma unroll
            for (int r = 0; r < 4; r++) acc[i][j][r] = 0.f;

    auto stage_load = [&](int st, int u0) {
#pragma unroll
        for (int rep = 0; rep < 4; rep++) {          // A: W tile 128x32 (natural [v][kk])
            int idx4 = rep * 256 + tid;
            int r = idx4 >> 3, c = idx4 & 7;
            cpa16(As[st] + r * SA + c * 4, g_Wt + (size_t)(v0 + r) * DM + u0 + c * 4);
        }
#pragma unroll
        for (int rep = 0; rep < 4; rep++) {          // B: g tile 32x128 ([kk][l])
            int idx4 = rep * 256 + tid;
            int r = idx4 >> 5, c = idx4 & 31;
            cpa16(Bs[st] + r * SB + c * 4, gbase + (size_t)(u0 + r) * LSEQ + l0 + c * 4);
        }
        asm volatile("cp.async.commit_group;\n");
    };

    stage_load(0, 0);

    const int NIT = DM / BK;                 // 32
    for (int it = 0; it < NIT; it++) {
        if (it + 1 < NIT) {
            stage_load((it + 1) & 1, (it + 1) * BK);
            asm volatile("cp.async.wait_group 1;\n");
        } else {
            asm volatile("cp.async.wait_group 0;\n");
        }
        __syncthreads();
        const unsigned* A = As[it & 1];
        const unsigned* Bsm = Bs[it & 1];
#pragma unroll
        for (int ks = 0; ks < BK; ks += 8) {
            unsigned bf[4][2];
#pragma unroll
            for (int nt = 0; nt < 4; nt++) {
                int cn = wn * 32 + nt * 8 + grp;
                bf[nt][0] = Bsm[(ks + qid) * SB + cn];
                bf[nt][1] = Bsm[(ks + qid + 4) * SB + cn];
            }
#pragma unroll
            for (int mt = 0; mt < 4; mt++) {
                int rowa = wm * 64 + mt * 16 + (lane & 15);
                int cola = ks + ((lane & 16) ? 4 : 0);
                unsigned a0, a1, a2, a3;
                ldsm4(a0, a1, a2, a3, A + rowa * SA + cola);
#pragma unroll
                for (int nt = 0; nt < 4; nt++) {
                    asm volatile(
                        "mma.sync.aligned.m16n8k8.row.col.f32.tf32.tf32.f32 "
                        "{%0,%1,%2,%3}, {%4,%5,%6,%7}, {%8,%9}, {%0,%1,%2,%3};\n"
                        : "+f"(acc[mt][nt][0]), "+f"(acc[mt][nt][1]),
                          "+f"(acc[mt][nt][2]), "+f"(acc[mt][nt][3])
                        : "r"(a0), "r"(a1), "r"(a2), "r"(a3),
                          "r"(bf[nt][0]), "r"(bf[nt][1]));
                }
            }
        }
        __syncthreads();
    }
#pragma unroll
    for (int mt = 0; mt < 4; mt++) {
        int v = v0 + wm * 64 + mt * 16 + grp;
        float bi0 = bias[v], bi1 = bias[v + 8];
#pragma unroll
        for (int nt = 0; nt < 4; nt++) {
            int l = l0 + wn * 32 + nt * 8 + qid * 2;
            float2* o0 = (float2*)(out + ((size_t)b * DM + v) * LSEQ + l);
            float2* o1 = (float2*)(out + ((size_t)b * DM + v + 8) * LSEQ + l);
            *o0 = make_float2(acc[mt][nt][0] + bi0, acc[mt][nt][1] + bi0);
            *o1 = make_float2(acc[mt][nt][2] + bi1, acc[mt][nt][3] + bi1);
        }
    }
}

// ---------------- launch ----------------
extern "C" void kernel_launch(void* const* d_in, const int* in_sizes, int n_in,
                              void* d_out, int out_size) {
    const float* u  = (const float*)d_in[0];
    const float* k0 = (const float*)d_in[1];
    const float* k1 = (const float*)d_in[2];
    const float* k2 = (const float*)d_in[3];
    const float* k3 = (const float*)d_in[4];
    const float* k4 = (const float*)d_in[5];
    const float* k5 = (const float*)d_in[6];
    const float* k6 = (const float*)d_in[7];
    const float* Dv = (const float*)d_in[8];
    const float* W  = (const float*)d_in[9];
    const float* bi = (const float*)d_in[10];
    float* out = (float*)d_out;

    const int smem_fft = (NF + S1PAD) * (int)sizeof(float2);             // 67584 B
    const int smem_gemm = 2 * (A_SZ + B_SZ) * (int)sizeof(unsigned);     // 71680 B
    cudaFuncSetAttribute(conv_kernel, cudaFuncAttributeMaxDynamicSharedMemorySize, smem_fft);
    cudaFuncSetAttribute(build_kf_kernel, cudaFuncAttributeMaxDynamicSharedMemorySize, smem_fft);
    cudaFuncSetAttribute(gemm_kernel, cudaFuncAttributeMaxDynamicSharedMemorySize, smem_gemm);

    init_tables_kernel<<<9, 256>>>();
    cvt_w_kernel<<<DM * DM / 256, 256>>>(W);
    build_kf_kernel<<<DM, 256, smem_fft>>>(k0, k1, k2, k3, k4, k5, k6);
    conv_kernel<<<BB * DM, 256, smem_fft>>>(u, Dv);
    dim3 gg(LSEQ / BN, DM / BM, BB);
    gemm_kernel<<<gg, 256, smem_gemm>>>(bi, out);
}

// round 5
// speedup vs baseline: 2.2179x; 1.1945x over previous
#include <cuda_runtime.h>
#include <math.h>

#define LSEQ 4096
#define DM   1024
#define BB   8
#define NF   4096          // complex FFT size (real FFT of 8192 via packing)
#define MH   4096          // half of 8192
#define SBUF 4352          // padded in-place buffer: 17 * 256 float2

// padded index map (avoids 128B-stride bank conflicts)
#define PHI(i) ((((i) >> 4) * 17) + ((i) & 15))

// ---------------- device scratch (no allocations allowed) ----------------
__device__ float2   g_Kf[DM * (MH + 1)];                 // kernel spectra (pre-scaled by 1/4096)
__device__ unsigned g_g[(size_t)BB * DM * LSEQ];         // gelu output as TF32 bits
__device__ unsigned g_Wt[DM * DM];                       // W as TF32 bits
__device__ float2   g_tw[NF / 2];                        // e^{-2pi i j/4096}
__device__ float2   g_tw2[MH / 2 + 1];                   // e^{-2pi i k/8192}

__device__ __forceinline__ float2 cmulf(float2 a, float2 b) {
    return make_float2(a.x * b.x - a.y * b.y, a.x * b.y + a.y * b.x);
}
__device__ __forceinline__ unsigned f2tf32(float f) {
    unsigned r;
    asm("cvt.rna.tf32.f32 %0, %1;" : "=r"(r) : "f"(f));
    return r;
}

// ---------------- twiddle tables ----------------
__global__ void init_tables_kernel() {
    int i = blockIdx.x * blockDim.x + threadIdx.x;
    if (i < NF / 2) {
        float a = (float)i / (float)(NF / 2);
        g_tw[i] = make_float2(cospif(a), -sinpif(a));
    }
    if (i <= MH / 2) {
        float a = (float)i / (float)MH;
        g_tw2[i] = make_float2(cospif(a), -sinpif(a));
    }
}

__global__ void cvt_w_kernel(const float* __restrict__ W) {
    int i = blockIdx.x * blockDim.x + threadIdx.x;
    if (i < DM * DM) g_Wt[i] = f2tf32(W[i]);
}

// ---------------- in-place 16-point DFT (two radix-4 stages) ----------------
// On exit, c[slot] = X[m(slot)] with m(slot) = 4*(slot&3) + (slot>>2).
// HZ: inputs c[8..15] treated as zero (not read).
template<int DIR, bool HZ>
__device__ __forceinline__ void dft16ip(float2* c) {
    const float d  = (float)DIR;
    const float C1 = 0.92387953251128674f;
    const float Sn = 0.38268343236508978f;
    const float HF = 0.70710678118654752f;
    // stage 1: columns r1 over slots {r1, r1+4, r1+8, r1+12}
#pragma unroll
    for (int r1 = 0; r1 < 4; r1++) {
        float2 a = c[r1], b = c[r1 + 4];
        if (HZ) {
            c[r1]      = make_float2(a.x + b.x, a.y + b.y);
            c[r1 + 4]  = make_float2(a.x + d * b.y, a.y - d * b.x);
            c[r1 + 8]  = make_float2(a.x - b.x, a.y - b.y);
            c[r1 + 12] = make_float2(a.x - d * b.y, a.y + d * b.x);
        } else {
            float2 e = c[r1 + 8], f = c[r1 + 12];
            float2 t0 = make_float2(a.x + e.x, a.y + e.y);
            float2 t1 = make_float2(a.x - e.x, a.y - e.y);
            float2 t2 = make_float2(b.x + f.x, b.y + f.y);
            float2 t3 = make_float2(b.x - f.x, b.y - f.y);
            c[r1]      = make_float2(t0.x + t2.x, t0.y + t2.y);
            c[r1 + 8]  = make_float2(t0.x - t2.x, t0.y - t2.y);
            c[r1 + 4]  = make_float2(t1.x + d * t3.y, t1.y - d * t3.x);
            c[r1 + 12] = make_float2(t1.x - d * t3.y, t1.y + d * t3.x);
        }
    }
    // inter-stage twiddles: slot r1+4*m1 *= w16^{r1*m1}
    const float2 e1 = make_float2(C1,  -d * Sn);
    const float2 e2 = make_float2(HF,  -d * HF);
    const float2 e3 = make_float2(Sn,  -d * C1);
    const float2 e6 = make_float2(-HF, -d * HF);
    const float2 e9 = make_float2(-C1,  d * Sn);
    c[5]  = cmulf(c[5],  e1);
    c[9]  = cmulf(c[9],  e2);
    c[13] = cmulf(c[13], e3);
    c[6]  = cmulf(c[6],  e2);
    c[10] = make_float2(d * c[10].y, -d * c[10].x);   // * w16^4 = -i*d
    c[14] = cmulf(c[14], e6);
    c[7]  = cmulf(c[7],  e3);
    c[11] = cmulf(c[11], e6);
    c[15] = cmulf(c[15], e9);
    // stage 2: groups m2 over slots {4m2 .. 4m2+3}
#pragma unroll
    for (int m2 = 0; m2 < 4; m2++) {
        float2 u0 = c[4 * m2], u1 = c[4 * m2 + 1], u2 = c[4 * m2 + 2], u3 = c[4 * m2 + 3];
        float2 t0 = make_float2(u0.x + u2.x, u0.y + u2.y);
        float2 t1 = make_float2(u0.x - u2.x, u0.y - u2.y);
        float2 t2 = make_float2(u1.x + u3.x, u1.y + u3.y);
        float2 t3 = make_float2(u1.x - u3.x, u1.y - u3.y);
        c[4 * m2]     = make_float2(t0.x + t2.x, t0.y + t2.y);
        c[4 * m2 + 2] = make_float2(t0.x - t2.x, t0.y - t2.y);
        c[4 * m2 + 1] = make_float2(t1.x + d * t3.y, t1.y - d * t3.x);
        c[4 * m2 + 3] = make_float2(t1.x - d * t3.y, t1.y + d * t3.x);
    }
}

// store with Stockham twiddle w1^m applied in permuted slot order:
// s[wbase + stride*m(slot)] = w1^{m(slot)} * c[slot]
__device__ __forceinline__ void store_tw(float2* s, int wbase, int stride,
                                         float2 w1, const float2* c) {
    float2 w2 = cmulf(w1, w1);
    float2 w4 = cmulf(w2, w2);
    float2 gw = make_float2(1.f, 0.f);
#pragma unroll
    for (int b = 0; b < 4; b++) {
        float2 w = gw;                                  // w1^{4b}
        s[wbase + stride * (4 * b + 0)] = cmulf(w, c[b]);
        w = cmulf(w, w1);
        s[wbase + stride * (4 * b + 1)] = cmulf(w, c[4 + b]);
        w = cmulf(w, w1);
        s[wbase + stride * (4 * b + 2)] = cmulf(w, c[8 + b]);
        w = cmulf(w, w1);
        s[wbase + stride * (4 * b + 3)] = cmulf(w, c[12 + b]);
        gw = cmulf(gw, w4);
    }
}

// ---------------- in-place radix-16 Stockham FFT, N=4096, 3 passes ----------------
// Logical element i lives at s[PHI(i)] before and after. Caller syncs before call.
template<int DIR, bool HZ>
__device__ __forceinline__ void fft4096_ip(float2* s, int tid) {
    float2 c[16];
    const int rb = PHI(tid);                 // read base; reads at rb + 272*m
    // ---- pass 0: out logical 16*tid + m -> addr 17*tid + m ----
    {
#pragma unroll
        for (int m = 0; m < (HZ ? 8 : 16); m++) c[m] = s[rb + 272 * m];
        dft16ip<DIR, HZ>(c);
        float2 w1 = g_tw[tid];
        if (DIR < 0) w1.y = -w1.y;
        __syncthreads();
        store_tw(s, 17 * tid, 1, w1, c);
        __syncthreads();
    }
    // ---- pass 1: out logical 16*(tid&~15) + (tid&15) + 16m -> addr base1 + 17*m ----
    {
#pragma unroll
        for (int m = 0; m < 16; m++) c[m] = s[rb + 272 * m];
        dft16ip<DIR, false>(c);
        float2 w1 = g_tw[tid & ~15];
        if (DIR < 0) w1.y = -w1.y;
        __syncthreads();
        store_tw(s, 17 * (tid & ~15) + (tid & 15), 17, w1, c);
        __syncthreads();
    }
    // ---- pass 2: out logical tid + 256m -> addr rb + 272*m; twiddles all 1 ----
    {
#pragma unroll
        for (int m = 0; m < 16; m++) c[m] = s[rb + 272 * m];
        dft16ip<DIR, false>(c);
        __syncthreads();
#pragma unroll
        for (int slot = 0; slot < 16; slot++) {
            int m = 4 * (slot & 3) + (slot >> 2);
            s[rb + 272 * m] = c[slot];
        }
        __syncthreads();
    }
}

// ---------------- build kernel spectrum: interp + norm + rfft ----------------
__global__ void build_kf_kernel(const float* __restrict__ k0, const float* __restrict__ k1,
                                const float* __restrict__ k2, const float* __restrict__ k3,
                                const float* __restrict__ k4, const float* __restrict__ k5,
                                const float* __restrict__ k6) {
    extern __shared__ float2 smem[];
    float2* s = smem;                // SBUF float2, padded PHI layout
    __shared__ float red[8];
    int d = blockIdx.x;
    int tid = threadIdx.x;

    const float* segp[7] = {k0, k1, k2, k3, k4, k5, k6};

    // interp: write unscaled value for tap t into packed complex slot (PHI layout)
    float ss = 0.f;
    for (int t = tid; t < LSEQ; t += 256) {
        int seg, scale, off;
        if      (t < 64)   { seg = 0; scale = 1;  off = 0;    }
        else if (t < 128)  { seg = 1; scale = 1;  off = 64;   }
        else if (t < 256)  { seg = 2; scale = 2;  off = 128;  }
        else if (t < 512)  { seg = 3; scale = 4;  off = 256;  }
        else if (t < 1024) { seg = 4; scale = 8;  off = 512;  }
        else if (t < 2048) { seg = 5; scale = 16; off = 1024; }
        else               { seg = 6; scale = 32; off = 2048; }
        int j = t - off;
        float coord = ((float)j + 0.5f) / (float)scale - 0.5f;
        coord = fminf(fmaxf(coord, 0.f), 63.f);
        int lo = (int)coord;
        int hi = min(lo + 1, 63);
        float w = coord - (float)lo;
        const float* kp = segp[seg] + d * 64;
        float v = kp[lo] * (1.f - w) + kp[hi] * w;
        ((float*)s)[2 * PHI(t >> 1) + (t & 1)] = v;
        ss += v * v;
    }
    for (int o = 16; o > 0; o >>= 1) ss += __shfl_xor_sync(0xffffffffu, ss, o);
    if ((tid & 31) == 0) red[tid >> 5] = ss;
    __syncthreads();
    float tot = 0.f;
#pragma unroll
    for (int i = 0; i < 8; i++) tot += red[i];
    float sc = 1.0f / sqrtf(tot);

    // normalize in place (lower half only; upper half unused by HZ fft)
    for (int n = tid; n < NF / 2; n += 256) {
        float2 z = s[PHI(n)];
        s[PHI(n)] = make_float2(z.x * sc, z.y * sc);
    }
    __syncthreads();
    fft4096_ip<1, true>(s, tid);

    // unpack packed-complex FFT -> rfft(8192) spectrum; fold 1/4096 inverse scale
    const float INV = 1.0f / 4096.0f;
    float2* Kf = g_Kf + (size_t)d * (MH + 1);
    for (int k = tid; k <= 2048; k += 256) {
        if (k == 0) {
            float2 Z0 = s[PHI(0)];
            Kf[0]  = make_float2((Z0.x + Z0.y) * INV, 0.f);
            Kf[MH] = make_float2((Z0.x - Z0.y) * INV, 0.f);
        } else if (k == 2048) {
            float2 Z = s[PHI(2048)];
            Kf[2048] = make_float2(Z.x * INV, -Z.y * INV);
        } else {
            float2 Za = s[PHI(k)], Zb = s[PHI(NF - k)];
            float2 E  = make_float2(0.5f * (Za.x + Zb.x), 0.5f * (Za.y - Zb.y));
            float2 Dm = make_float2(0.5f * (Za.x - Zb.x), 0.5f * (Za.y + Zb.y));
            float2 O  = make_float2(Dm.y, -Dm.x);
            float2 w  = g_tw2[k];
            float2 WO = cmulf(w, O);
            Kf[k]      = make_float2((E.x + WO.x) * INV, (E.y + WO.y) * INV);
            Kf[MH - k] = make_float2((E.x - WO.x) * INV, -(E.y - WO.y) * INV);
        }
    }
}

// ---------------- per-row conv: rfft(u) * Kf -> irfft -> skip -> gelu -> tf32 ----------------
__global__ void __launch_bounds__(256, 4) conv_kernel(const float* __restrict__ u,
                                                      const float* __restrict__ Dv) {
    extern __shared__ float2 smem[];
    float2* s = smem;                // SBUF float2, padded PHI layout
    int row = blockIdx.x;            // b*DM + d
    int d = row & (DM - 1);
    int tid = threadIdx.x;
    const float2* u2 = (const float2*)(u + (size_t)row * LSEQ);

    for (int n = tid; n < 2048; n += 256) s[PHI(n)] = u2[n];   // pack even/odd; upper half HZ
    __syncthreads();
    fft4096_ip<1, true>(s, tid);

    // spectral: unpack X, multiply by Kf, repack Z' for inverse. In place (disjoint pairs).
    const float2* Kf = g_Kf + (size_t)d * (MH + 1);
    for (int k = tid; k <= 2048; k += 256) {
        if (k == 0) {
            float2 Z0 = s[PHI(0)];
            float X0 = Z0.x + Z0.y;
            float XM = Z0.x - Z0.y;
            float2 K0 = Kf[0], KM = Kf[MH];
            float2 Y0 = make_float2(X0 * K0.x, X0 * K0.y);
            float2 YM = make_float2(XM * KM.x, XM * KM.y);
            float2 Ep = make_float2(0.5f * (Y0.x + YM.x), 0.5f * (Y0.y - YM.y));
            float2 Op = make_float2(0.5f * (Y0.x - YM.x), 0.5f * (Y0.y + YM.y));
            s[PHI(0)] = make_float2(Ep.x - Op.y, Ep.y + Op.x);
        } else if (k == 2048) {
            float2 Z = s[PHI(2048)];
            float2 X = make_float2(Z.x, -Z.y);
            float2 Y = cmulf(X, Kf[2048]);
            s[PHI(2048)] = make_float2(Y.x, -Y.y);
        } else {
            float2 Za = s[PHI(k)], Zb = s[PHI(NF - k)];
            float2 E  = make_float2(0.5f * (Za.x + Zb.x), 0.5f * (Za.y - Zb.y));
            float2 Dm = make_float2(0.5f * (Za.x - Zb.x), 0.5f * (Za.y + Zb.y));
            float2 O  = make_float2(Dm.y, -Dm.x);
            float2 w  = g_tw2[k];
            float2 WO = cmulf(w, O);
            float2 Xa = make_float2(E.x + WO.x, E.y + WO.y);
            float2 Xb = make_float2(E.x - WO.x, -(E.y - WO.y));
            float2 Ya = cmulf(Xa, Kf[k]);
            float2 Yb = cmulf(Xb, Kf[MH - k]);
            float2 Ep = make_float2(0.5f * (Ya.x + Yb.x), 0.5f * (Ya.y - Yb.y));
            float2 Dp = make_float2(0.5f * (Ya.x - Yb.x), 0.5f * (Ya.y + Yb.y));
            float2 V  = make_float2(w.x, -w.y);
            float2 Op = cmulf(V, Dp);
            s[PHI(k)]      = make_float2(Ep.x - Op.y, Ep.y + Op.x);
            s[PHI(NF - k)] = make_float2(Ep.x + Op.y, Op.x - Ep.y);
        }
    }
    __syncthreads();
    fft4096_ip<-1, false>(s, tid);

    float Dd = Dv[d];
    uint2* gout = (uint2*)(g_g + (size_t)row * LSEQ);
#pragma unroll 1
    for (int n = tid; n < 2048; n += 256) {
        float2 z = s[PHI(n)];                // 1/4096 already folded into Kf
        float2 uu = u2[n];
        float x0 = z.x + uu.x * Dd;
        float x1 = z.y + uu.y * Dd;
        float g0 = 0.5f * x0 * (1.f + erff(x0 * 0.70710678118654752f));
        float g1 = 0.5f * x1 * (1.f + erff(x1 * 0.70710678118654752f));
        gout[n] = make_uint2(f2tf32(g0), f2tf32(g1));
    }
}

// ---------------- TF32 tensor-core GEMM: out[b,v,l] = sum_u W[v,u] g[b,u,l] + bias[v] ----
#define BM 128
#define BN 128
#define BK 32
#define SA 36     // As row stride (floats): [v][kk]
#define SB 136    // Bs row stride (floats): [kk][l]
#define A_SZ (BM * SA)
#define B_SZ (BK * SB)

__device__ __forceinline__ void cpa16(void* s, const void* g) {
    unsigned sa = (unsigned)__cvta_generic_to_shared(s);
    asm volatile("cp.async.cg.shared.global [%0], [%1], 16;\n" :: "r"(sa), "l"(g));
}
__device__ __forceinline__ void ldsm4(unsigned& r0, unsigned& r1, unsigned& r2, unsigned& r3,
                                      const void* p) {
    unsigned a = (unsigned)__cvta_generic_to_shared(p);
    asm volatile("ldmatrix.sync.aligned.m8n8.x4.shared.b16 {%0,%1,%2,%3}, [%4];\n"
                 : "=r"(r0), "=r"(r1), "=r"(r2), "=r"(r3) : "r"(a));
}

__global__ void __launch_bounds__(256) gemm_kernel(const float* __restrict__ bias,
                                                   float* __restrict__ out) {
    extern __shared__ unsigned gsm[];
    unsigned* As[2] = {gsm, gsm + A_SZ + B_SZ};
    unsigned* Bs[2] = {gsm + A_SZ, gsm + 2 * A_SZ + B_SZ};

    int b  = blockIdx.z;
    int v0 = blockIdx.y * BM;
    int l0 = blockIdx.x * BN;
    int tid = threadIdx.x;
    int wid = tid >> 5, lane = tid & 31;
    int wm = wid >> 2, wn = wid & 3;         // 2x4 warp grid; warp tile 64(v) x 32(l)
    int grp = lane >> 2, qid = lane & 3;

    const unsigned* gbase = g_g + (size_t)b * DM * LSEQ;

    float acc[4][4][4];
#pragma unroll
    for (int i = 0; i < 4; i++)
#pragma unroll
        for (int j = 0; j < 4; j++)
#pragma unroll
            for (int r = 0; r < 4; r++) acc[i][j][r] = 0.f;

    auto stage_load = [&](int st, int u0) {
#pragma unroll
        for (int rep = 0; rep < 4; rep++) {          // A: W tile 128x32 (natural [v][kk])
            int idx4 = rep * 256 + tid;
            int r = idx4 >> 3, c = idx4 & 7;
            cpa16(As[st] + r * SA + c * 4, g_Wt + (size_t)(v0 + r) * DM + u0 + c * 4);
        }
#pragma unroll
        for (int rep = 0; rep < 4; rep++) {          // B: g tile 32x128 ([kk][l])
            int idx4 = rep * 256 + tid;
            int r = idx4 >> 5, c = idx4 & 31;
            cpa16(Bs[st] + r * SB + c * 4, gbase + (size_t)(u0 + r) * LSEQ + l0 + c * 4);
        }
        asm volatile("cp.async.commit_group;\n");
    };

    stage_load(0, 0);

    const int NIT = DM / BK;                 // 32
    for (int it = 0; it < NIT; it++) {
        if (it + 1 < NIT) {
            stage_load((it + 1) & 1, (it + 1) * BK);
            asm volatile("cp.async.wait_group 1;\n");
        } else {
            asm volatile("cp.async.wait_group 0;\n");
        }
        __syncthreads();
        const unsigned* A = As[it & 1];
        const unsigned* Bsm = Bs[it & 1];
#pragma unroll
        for (int ks = 0; ks < BK; ks += 8) {
            unsigned bf[4][2];
#pragma unroll
            for (int nt = 0; nt < 4; nt++) {
                int cn = wn * 32 + nt * 8 + grp;
                bf[nt][0] = Bsm[(ks + qid) * SB + cn];
                bf[nt][1] = Bsm[(ks + qid + 4) * SB + cn];
            }
#pragma unroll
            for (int mt = 0; mt < 4; mt++) {
                int rowa = wm * 64 + mt * 16 + (lane & 15);
                int cola = ks + ((lane & 16) ? 4 : 0);
                unsigned a0, a1, a2, a3;
                ldsm4(a0, a1, a2, a3, A + rowa * SA + cola);
#pragma unroll
                for (int nt = 0; nt < 4; nt++) {
                    asm volatile(
                        "mma.sync.aligned.m16n8k8.row.col.f32.tf32.tf32.f32 "
                        "{%0,%1,%2,%3}, {%4,%5,%6,%7}, {%8,%9}, {%0,%1,%2,%3};\n"
                        : "+f"(acc[mt][nt][0]), "+f"(acc[mt][nt][1]),
                          "+f"(acc[mt][nt][2]), "+f"(acc[mt][nt][3])
                        : "r"(a0), "r"(a1), "r"(a2), "r"(a3),
                          "r"(bf[nt][0]), "r"(bf[nt][1]));
                }
            }
        }
        __syncthreads();
    }
#pragma unroll
    for (int mt = 0; mt < 4; mt++) {
        int v = v0 + wm * 64 + mt * 16 + grp;
        float bi0 = bias[v], bi1 = bias[v + 8];
#pragma unroll
        for (int nt = 0; nt < 4; nt++) {
            int l = l0 + wn * 32 + nt * 8 + qid * 2;
            float2* o0 = (float2*)(out + ((size_t)b * DM + v) * LSEQ + l);
            float2* o1 = (float2*)(out + ((size_t)b * DM + v + 8) * LSEQ + l);
            *o0 = make_float2(acc[mt][nt][0] + bi0, acc[mt][nt][1] + bi0);
            *o1 = make_float2(acc[mt][nt][2] + bi1, acc[mt][nt][3] + bi1);
        }
    }
}

// ---------------- launch ----------------
extern "C" void kernel_launch(void* const* d_in, const int* in_sizes, int n_in,
                              void* d_out, int out_size) {
    const float* u  = (const float*)d_in[0];
    const float* k0 = (const float*)d_in[1];
    const float* k1 = (const float*)d_in[2];
    const float* k2 = (const float*)d_in[3];
    const float* k3 = (const float*)d_in[4];
    const float* k4 = (const float*)d_in[5];
    const float* k5 = (const float*)d_in[6];
    const float* k6 = (const float*)d_in[7];
    const float* Dv = (const float*)d_in[8];
    const float* W  = (const float*)d_in[9];
    const float* bi = (const float*)d_in[10];
    float* out = (float*)d_out;

    const int smem_fft = SBUF * (int)sizeof(float2);                     // 34816 B
    const int smem_gemm = 2 * (A_SZ + B_SZ) * (int)sizeof(unsigned);     // 71680 B
    cudaFuncSetAttribute(conv_kernel, cudaFuncAttributeMaxDynamicSharedMemorySize, smem_fft);
    cudaFuncSetAttribute(build_kf_kernel, cudaFuncAttributeMaxDynamicSharedMemorySize, smem_fft);
    cudaFuncSetAttribute(gemm_kernel, cudaFuncAttributeMaxDynamicSharedMemorySize, smem_gemm);

    init_tables_kernel<<<9, 256>>>();
    cvt_w_kernel<<<DM * DM / 256, 256>>>(W);
    build_kf_kernel<<<DM, 256, smem_fft>>>(k0, k1, k2, k3, k4, k5, k6);
    conv_kernel<<<BB * DM, 256, smem_fft>>>(u, Dv);
    dim3 gg(LSEQ / BN, DM / BM, BB);
    gemm_kernel<<<gg, 256, smem_gemm>>>(bi, out);
}

// round 6
// speedup vs baseline: 2.2440x; 1.0118x over previous
#include <cuda_runtime.h>
#include <math.h>

#define LSEQ 4096
#define DM   1024
#define BB   8
#define NF   4096          // complex FFT size (real FFT of 8192 via packing)
#define MH   4096          // half of 8192
#define SBUF 4352          // padded in-place buffer: 17 * 256 float2

// padded index map (avoids 128B-stride bank conflicts)
#define PHI(i) ((((i) >> 4) * 17) + ((i) & 15))

// ---------------- device scratch (no allocations allowed) ----------------
__device__ float2   g_Kf[DM * (MH + 1)];                 // kernel spectra (pre-scaled by 1/4096)
__device__ unsigned g_g[(size_t)BB * DM * LSEQ];         // gelu output as TF32 bits
__device__ unsigned g_Wt[DM * DM];                       // W as TF32 bits
__device__ float2   g_tw[NF / 2];                        // e^{-2pi i j/4096}
__device__ float2   g_tw2[MH / 2 + 1];                   // e^{-2pi i k/8192}

__device__ __forceinline__ float2 cmulf(float2 a, float2 b) {
    return make_float2(a.x * b.x - a.y * b.y, a.x * b.y + a.y * b.x);
}
__device__ __forceinline__ unsigned f2tf32(float f) {
    unsigned r;
    asm("cvt.rna.tf32.f32 %0, %1;" : "=r"(r) : "f"(f));
    return r;
}

// ---------------- twiddle tables ----------------
__global__ void init_tables_kernel() {
    int i = blockIdx.x * blockDim.x + threadIdx.x;
    if (i < NF / 2) {
        float a = (float)i / (float)(NF / 2);
        g_tw[i] = make_float2(cospif(a), -sinpif(a));
    }
    if (i <= MH / 2) {
        float a = (float)i / (float)MH;
        g_tw2[i] = make_float2(cospif(a), -sinpif(a));
    }
}

__global__ void cvt_w_kernel(const float* __restrict__ W) {
    int i = blockIdx.x * blockDim.x + threadIdx.x;
    if (i < DM * DM) g_Wt[i] = f2tf32(W[i]);
}

// ---------------- in-place 16-point DFT (two radix-4 stages) ----------------
// On exit, c[slot] = X[m(slot)] with m(slot) = 4*(slot&3) + (slot>>2).
// HZ: inputs c[8..15] treated as zero (not read).
template<int DIR, bool HZ>
__device__ __forceinline__ void dft16ip(float2* c) {
    const float d  = (float)DIR;
    const float C1 = 0.92387953251128674f;
    const float Sn = 0.38268343236508978f;
    const float HF = 0.70710678118654752f;
#pragma unroll
    for (int r1 = 0; r1 < 4; r1++) {
        float2 a = c[r1], b = c[r1 + 4];
        if (HZ) {
            c[r1]      = make_float2(a.x + b.x, a.y + b.y);
            c[r1 + 4]  = make_float2(a.x + d * b.y, a.y - d * b.x);
            c[r1 + 8]  = make_float2(a.x - b.x, a.y - b.y);
            c[r1 + 12] = make_float2(a.x - d * b.y, a.y + d * b.x);
        } else {
            float2 e = c[r1 + 8], f = c[r1 + 12];
            float2 t0 = make_float2(a.x + e.x, a.y + e.y);
            float2 t1 = make_float2(a.x - e.x, a.y - e.y);
            float2 t2 = make_float2(b.x + f.x, b.y + f.y);
            float2 t3 = make_float2(b.x - f.x, b.y - f.y);
            c[r1]      = make_float2(t0.x + t2.x, t0.y + t2.y);
            c[r1 + 8]  = make_float2(t0.x - t2.x, t0.y - t2.y);
            c[r1 + 4]  = make_float2(t1.x + d * t3.y, t1.y - d * t3.x);
            c[r1 + 12] = make_float2(t1.x - d * t3.y, t1.y + d * t3.x);
        }
    }
    const float2 e1 = make_float2(C1,  -d * Sn);
    const float2 e2 = make_float2(HF,  -d * HF);
    const float2 e3 = make_float2(Sn,  -d * C1);
    const float2 e6 = make_float2(-HF, -d * HF);
    const float2 e9 = make_float2(-C1,  d * Sn);
    c[5]  = cmulf(c[5],  e1);
    c[9]  = cmulf(c[9],  e2);
    c[13] = cmulf(c[13], e3);
    c[6]  = cmulf(c[6],  e2);
    c[10] = make_float2(d * c[10].y, -d * c[10].x);   // * w16^4 = -i*d
    c[14] = cmulf(c[14], e6);
    c[7]  = cmulf(c[7],  e3);
    c[11] = cmulf(c[11], e6);
    c[15] = cmulf(c[15], e9);
#pragma unroll
    for (int m2 = 0; m2 < 4; m2++) {
        float2 u0 = c[4 * m2], u1 = c[4 * m2 + 1], u2 = c[4 * m2 + 2], u3 = c[4 * m2 + 3];
        float2 t0 = make_float2(u0.x + u2.x, u0.y + u2.y);
        float2 t1 = make_float2(u0.x - u2.x, u0.y - u2.y);
        float2 t2 = make_float2(u1.x + u3.x, u1.y + u3.y);
        float2 t3 = make_float2(u1.x - u3.x, u1.y - u3.y);
        c[4 * m2]     = make_float2(t0.x + t2.x, t0.y + t2.y);
        c[4 * m2 + 2] = make_float2(t0.x - t2.x, t0.y - t2.y);
        c[4 * m2 + 1] = make_float2(t1.x + d * t3.y, t1.y - d * t3.x);
        c[4 * m2 + 3] = make_float2(t1.x - d * t3.y, t1.y + d * t3.x);
    }
}

// store with Stockham twiddle w1^m applied in permuted slot order
__device__ __forceinline__ void store_tw(float2* s, int wbase, int stride,
                                         float2 w1, const float2* c) {
    float2 w2 = cmulf(w1, w1);
    float2 w4 = cmulf(w2, w2);
    float2 gw = make_float2(1.f, 0.f);
#pragma unroll
    for (int b = 0; b < 4; b++) {
        float2 w = gw;
        s[wbase + stride * (4 * b + 0)] = cmulf(w, c[b]);
        w = cmulf(w, w1);
        s[wbase + stride * (4 * b + 1)] = cmulf(w, c[4 + b]);
        w = cmulf(w, w1);
        s[wbase + stride * (4 * b + 2)] = cmulf(w, c[8 + b]);
        w = cmulf(w, w1);
        s[wbase + stride * (4 * b + 3)] = cmulf(w, c[12 + b]);
        gw = cmulf(gw, w4);
    }
}

// ---------------- in-place radix-16 Stockham FFT, N=4096, 3 passes ----------------
template<int DIR, bool HZ>
__device__ __forceinline__ void fft4096_ip(float2* s, int tid) {
    float2 c[16];
    const int rb = PHI(tid);
    {
#pragma unroll
        for (int m = 0; m < (HZ ? 8 : 16); m++) c[m] = s[rb + 272 * m];
        dft16ip<DIR, HZ>(c);
        float2 w1 = g_tw[tid];
        if (DIR < 0) w1.y = -w1.y;
        __syncthreads();
        store_tw(s, 17 * tid, 1, w1, c);
        __syncthreads();
    }
    {
#pragma unroll
        for (int m = 0; m < 16; m++) c[m] = s[rb + 272 * m];
        dft16ip<DIR, false>(c);
        float2 w1 = g_tw[tid & ~15];
        if (DIR < 0) w1.y = -w1.y;
        __syncthreads();
        store_tw(s, 17 * (tid & ~15) + (tid & 15), 17, w1, c);
        __syncthreads();
    }
    {
#pragma unroll
        for (int m = 0; m < 16; m++) c[m] = s[rb + 272 * m];
        dft16ip<DIR, false>(c);
        __syncthreads();
#pragma unroll
        for (int slot = 0; slot < 16; slot++) {
            int m = 4 * (slot & 3) + (slot >> 2);
            s[rb + 272 * m] = c[slot];
        }
        __syncthreads();
    }
}

// ---------------- build kernel spectrum: interp + norm + rfft ----------------
__global__ void build_kf_kernel(const float* __restrict__ k0, const float* __restrict__ k1,
                                const float* __restrict__ k2, const float* __restrict__ k3,
                                const float* __restrict__ k4, const float* __restrict__ k5,
                                const float* __restrict__ k6) {
    extern __shared__ float2 smem[];
    float2* s = smem;
    __shared__ float red[8];
    int d = blockIdx.x;
    int tid = threadIdx.x;

    const float* segp[7] = {k0, k1, k2, k3, k4, k5, k6};

    float ss = 0.f;
    for (int t = tid; t < LSEQ; t += 256) {
        int seg, scale, off;
        if      (t < 64)   { seg = 0; scale = 1;  off = 0;    }
        else if (t < 128)  { seg = 1; scale = 1;  off = 64;   }
        else if (t < 256)  { seg = 2; scale = 2;  off = 128;  }
        else if (t < 512)  { seg = 3; scale = 4;  off = 256;  }
        else if (t < 1024) { seg = 4; scale = 8;  off = 512;  }
        else if (t < 2048) { seg = 5; scale = 16; off = 1024; }
        else               { seg = 6; scale = 32; off = 2048; }
        int j = t - off;
        float coord = ((float)j + 0.5f) / (float)scale - 0.5f;
        coord = fminf(fmaxf(coord, 0.f), 63.f);
        int lo = (int)coord;
        int hi = min(lo + 1, 63);
        float w = coord - (float)lo;
        const float* kp = segp[seg] + d * 64;
        float v = kp[lo] * (1.f - w) + kp[hi] * w;
        ((float*)s)[2 * PHI(t >> 1) + (t & 1)] = v;
        ss += v * v;
    }
    for (int o = 16; o > 0; o >>= 1) ss += __shfl_xor_sync(0xffffffffu, ss, o);
    if ((tid & 31) == 0) red[tid >> 5] = ss;
    __syncthreads();
    float tot = 0.f;
#pragma unroll
    for (int i = 0; i < 8; i++) tot += red[i];
    float sc = 1.0f / sqrtf(tot);

    for (int n = tid; n < NF / 2; n += 256) {
        float2 z = s[PHI(n)];
        s[PHI(n)] = make_float2(z.x * sc, z.y * sc);
    }
    __syncthreads();
    fft4096_ip<1, true>(s, tid);

    const float INV = 1.0f / 4096.0f;
    float2* Kf = g_Kf + (size_t)d * (MH + 1);
    for (int k = tid; k <= 2048; k += 256) {
        if (k == 0) {
            float2 Z0 = s[PHI(0)];
            Kf[0]  = make_float2((Z0.x + Z0.y) * INV, 0.f);
            Kf[MH] = make_float2((Z0.x - Z0.y) * INV, 0.f);
        } else if (k == 2048) {
            float2 Z = s[PHI(2048)];
            Kf[2048] = make_float2(Z.x * INV, -Z.y * INV);
        } else {
            float2 Za = s[PHI(k)], Zb = s[PHI(NF - k)];
            float2 E  = make_float2(0.5f * (Za.x + Zb.x), 0.5f * (Za.y - Zb.y));
            float2 Dm = make_float2(0.5f * (Za.x - Zb.x), 0.5f * (Za.y + Zb.y));
            float2 O  = make_float2(Dm.y, -Dm.x);
            float2 w  = g_tw2[k];
            float2 WO = cmulf(w, O);
            Kf[k]      = make_float2((E.x + WO.x) * INV, (E.y + WO.y) * INV);
            Kf[MH - k] = make_float2((E.x - WO.x) * INV, -(E.y - WO.y) * INV);
        }
    }
}

// ---------------- per-row conv: rfft(u) * Kf -> irfft -> skip -> gelu -> tf32 ----------------
__global__ void __launch_bounds__(256, 4) conv_kernel(const float* __restrict__ u,
                                                      const float* __restrict__ Dv) {
    extern __shared__ float2 smem[];
    float2* s = smem;
    int row = blockIdx.x;            // b*DM + d
    int d = row & (DM - 1);
    int tid = threadIdx.x;
    const float2* u2 = (const float2*)(u + (size_t)row * LSEQ);

    for (int n = tid; n < 2048; n += 256) s[PHI(n)] = u2[n];
    __syncthreads();
    fft4096_ip<1, true>(s, tid);

    const float2* Kf = g_Kf + (size_t)d * (MH + 1);
    for (int k = tid; k <= 2048; k += 256) {
        if (k == 0) {
            float2 Z0 = s[PHI(0)];
            float X0 = Z0.x + Z0.y;
            float XM = Z0.x - Z0.y;
            float2 K0 = Kf[0], KM = Kf[MH];
            float2 Y0 = make_float2(X0 * K0.x, X0 * K0.y);
            float2 YM = make_float2(XM * KM.x, XM * KM.y);
            float2 Ep = make_float2(0.5f * (Y0.x + YM.x), 0.5f * (Y0.y - YM.y));
            float2 Op = make_float2(0.5f * (Y0.x - YM.x), 0.5f * (Y0.y + YM.y));
            s[PHI(0)] = make_float2(Ep.x - Op.y, Ep.y + Op.x);
        } else if (k == 2048) {
            float2 Z = s[PHI(2048)];
            float2 X = make_float2(Z.x, -Z.y);
            float2 Y = cmulf(X, Kf[2048]);
            s[PHI(2048)] = make_float2(Y.x, -Y.y);
        } else {
            float2 Za = s[PHI(k)], Zb = s[PHI(NF - k)];
            float2 E  = make_float2(0.5f * (Za.x + Zb.x), 0.5f * (Za.y - Zb.y));
            float2 Dm = make_float2(0.5f * (Za.x - Zb.x), 0.5f * (Za.y + Zb.y));
            float2 O  = make_float2(Dm.y, -Dm.x);
            float2 w  = g_tw2[k];
            float2 WO = cmulf(w, O);
            float2 Xa = make_float2(E.x + WO.x, E.y + WO.y);
            float2 Xb = make_float2(E.x - WO.x, -(E.y - WO.y));
            float2 Ya = cmulf(Xa, Kf[k]);
            float2 Yb = cmulf(Xb, Kf[MH - k]);
            float2 Ep = make_float2(0.5f * (Ya.x + Yb.x), 0.5f * (Ya.y - Yb.y));
            float2 Dp = make_float2(0.5f * (Ya.x - Yb.x), 0.5f * (Ya.y + Yb.y));
            float2 V  = make_float2(w.x, -w.y);
            float2 Op = cmulf(V, Dp);
            s[PHI(k)]      = make_float2(Ep.x - Op.y, Ep.y + Op.x);
            s[PHI(NF - k)] = make_float2(Ep.x + Op.y, Op.x - Ep.y);
        }
    }
    __syncthreads();
    fft4096_ip<-1, false>(s, tid);

    float Dd = Dv[d];
    uint2* gout = (uint2*)(g_g + (size_t)row * LSEQ);
#pragma unroll 1
    for (int n = tid; n < 2048; n += 256) {
        float2 z = s[PHI(n)];
        float2 uu = u2[n];
        float x0 = z.x + uu.x * Dd;
        float x1 = z.y + uu.y * Dd;
        float g0 = 0.5f * x0 * (1.f + erff(x0 * 0.70710678118654752f));
        float g1 = 0.5f * x1 * (1.f + erff(x1 * 0.70710678118654752f));
        gout[n] = make_uint2(f2tf32(g0), f2tf32(g1));
    }
}

// ---------------- TF32 tensor-core GEMM: out[b,v,l] = sum_u W[v,u] g[b,u,l] + bias[v] ----
#define BM 128
#define BN 128
#define BK 32
#define SA 36     // As row stride (words): [v][kk]
#define SB 136    // Bs row stride (words): [kk][l]
#define A_SZ (BM * SA)
#define B_SZ (BK * SB)

__device__ __forceinline__ void cpa16(void* s, const void* g) {
    unsigned sa = (unsigned)__cvta_generic_to_shared(s);
    asm volatile("cp.async.cg.shared.global [%0], [%1], 16;\n" :: "r"(sa), "l"(g));
}
__device__ __forceinline__ void ldsm4(unsigned& r0, unsigned& r1, unsigned& r2, unsigned& r3,
                                      const void* p) {
    unsigned a = (unsigned)__cvta_generic_to_shared(p);
    asm volatile("ldmatrix.sync.aligned.m8n8.x4.shared.b16 {%0,%1,%2,%3}, [%4];\n"
                 : "=r"(r0), "=r"(r1), "=r"(r2), "=r"(r3) : "r"(a));
}

__global__ void __launch_bounds__(256, 2) gemm_kernel(const float* __restrict__ bias,
                                                      float* __restrict__ out) {
    extern __shared__ unsigned gsm[];
    unsigned* As[2] = {gsm, gsm + A_SZ + B_SZ};
    unsigned* Bs[2] = {gsm + A_SZ, gsm + 2 * A_SZ + B_SZ};

    int b  = blockIdx.z;
    int v0 = blockIdx.y * BM;
    int l0 = blockIdx.x * BN;
    int tid = threadIdx.x;
    int wid = tid >> 5, lane = tid & 31;
    int wm = wid >> 2, wn = wid & 3;         // 2x4 warp grid; warp tile 64(v) x 32(l)
    int grp = lane >> 2, qid = lane & 3;

    const unsigned* gbase = g_g + (size_t)b * DM * LSEQ;

    float acc[4][4][4];
#pragma unroll
    for (int i = 0; i < 4; i++)
#pragma unroll
        for (int j = 0; j < 4; j++)
#pragma unroll
            for (int r = 0; r < 4; r++) acc[i][j][r] = 0.f;

    auto stage_load = [&](int st, int u0) {
#pragma unroll
        for (int rep = 0; rep < 4; rep++) {          // A: W tile 128x32 (natural [v][kk])
            int idx4 = rep * 256 + tid;
            int r = idx4 >> 3, c = idx4 & 7;
            cpa16(As[st] + r * SA + c * 4, g_Wt + (size_t)(v0 + r) * DM + u0 + c * 4);
        }
#pragma unroll
        for (int rep = 0; rep < 4; rep++) {          // B: g tile 32x128 ([kk][l])
            int idx4 = rep * 256 + tid;
            int r = idx4 >> 5, c = idx4 & 31;
            cpa16(Bs[st] + r * SB + c * 4, gbase + (size_t)(u0 + r) * LSEQ + l0 + c * 4);
        }
        asm volatile("cp.async.commit_group;\n");
    };

    stage_load(0, 0);

    const int NIT = DM / BK;                 // 32
    for (int it = 0; it < NIT; it++) {
        asm volatile("cp.async.wait_group 0;\n");    // stage it arrived (this thread)
        __syncthreads();                             // visible to all; prior reads done
        if (it + 1 < NIT) stage_load((it + 1) & 1, (it + 1) * BK);  // overlaps compute
        const unsigned* A = As[it & 1];
        const unsigned* Bsm = Bs[it & 1];

        // B fragments: double-buffered across ks-steps
        unsigned bf[2][4][2];
        {
            const unsigned* r0 = Bsm + qid * SB + wn * 32 + grp;
            const unsigned* r1 = Bsm + (qid + 4) * SB + wn * 32 + grp;
#pragma unroll
            for (int nt = 0; nt < 4; nt++) {
                bf[0][nt][0] = r0[nt * 8];
                bf[0][nt][1] = r1[nt * 8];
            }
        }
#pragma unroll
        for (int ks4 = 0; ks4 < 4; ks4++) {
            int cur = ks4 & 1;
            if (ks4 < 3) {
                int ksn = (ks4 + 1) * 8;
                const unsigned* r0 = Bsm + (ksn + qid) * SB + wn * 32 + grp;
                const unsigned* r1 = Bsm + (ksn + qid + 4) * SB + wn * 32 + grp;
#pragma unroll
                for (int nt = 0; nt < 4; nt++) {
                    bf[cur ^ 1][nt][0] = r0[nt * 8];
                    bf[cur ^ 1][nt][1] = r1[nt * 8];
                }
            }
#pragma unroll
            for (int mt = 0; mt < 4; mt++) {
                int rowa = wm * 64 + mt * 16 + (lane & 15);
                int cola = ks4 * 8 + ((lane & 16) ? 4 : 0);
                unsigned a0, a1, a2, a3;
                ldsm4(a0, a1, a2, a3, A + rowa * SA + cola);
#pragma unroll
                for (int nt = 0; nt < 4; nt++) {
                    asm volatile(
                        "mma.sync.aligned.m16n8k8.row.col.f32.tf32.tf32.f32 "
                        "{%0,%1,%2,%3}, {%4,%5,%6,%7}, {%8,%9}, {%0,%1,%2,%3};\n"
                        : "+f"(acc[mt][nt][0]), "+f"(acc[mt][nt][1]),
                          "+f"(acc[mt][nt][2]), "+f"(acc[mt][nt][3])
                        : "r"(a0), "r"(a1), "r"(a2), "r"(a3),
                          "r"(bf[cur][nt][0]), "r"(bf[cur][nt][1]));
                }
            }
        }
    }
#pragma unroll
    for (int mt = 0; mt < 4; mt++) {
        int v = v0 + wm * 64 + mt * 16 + grp;
        float bi0 = bias[v], bi1 = bias[v + 8];
#pragma unroll
        for (int nt = 0; nt < 4; nt++) {
            int l = l0 + wn * 32 + nt * 8 + qid * 2;
            float2* o0 = (float2*)(out + ((size_t)b * DM + v) * LSEQ + l);
            float2* o1 = (float2*)(out + ((size_t)b * DM + v + 8) * LSEQ + l);
            *o0 = make_float2(acc[mt][nt][0] + bi0, acc[mt][nt][1] + bi0);
            *o1 = make_float2(acc[mt][nt][2] + bi1, acc[mt][nt][3] + bi1);
        }
    }
}

// ---------------- launch ----------------
extern "C" void kernel_launch(void* const* d_in, const int* in_sizes, int n_in,
                              void* d_out, int out_size) {
    const float* u  = (const float*)d_in[0];
    const float* k0 = (const float*)d_in[1];
    const float* k1 = (const float*)d_in[2];
    const float* k2 = (const float*)d_in[3];
    const float* k3 = (const float*)d_in[4];
    const float* k4 = (const float*)d_in[5];
    const float* k5 = (const float*)d_in[6];
    const float* k6 = (const float*)d_in[7];
    const float* Dv = (const float*)d_in[8];
    const float* W  = (const float*)d_in[9];
    const float* bi = (const float*)d_in[10];
    float* out = (float*)d_out;

    const int smem_fft = SBUF * (int)sizeof(float2);                     // 34816 B
    const int smem_gemm = 2 * (A_SZ + B_SZ) * (int)sizeof(unsigned);     // 71680 B
    cudaFuncSetAttribute(conv_kernel, cudaFuncAttributeMaxDynamicSharedMemorySize, smem_fft);
    cudaFuncSetAttribute(build_kf_kernel, cudaFuncAttributeMaxDynamicSharedMemorySize, smem_fft);
    cudaFuncSetAttribute(gemm_kernel, cudaFuncAttributeMaxDynamicSharedMemorySize, smem_gemm);

    init_tables_kernel<<<9, 256>>>();
    cvt_w_kernel<<<DM * DM / 256, 256>>>(W);
    build_kf_kernel<<<DM, 256, smem_fft>>>(k0, k1, k2, k3, k4, k5, k6);
    conv_kernel<<<BB * DM, 256, smem_fft>>>(u, Dv);
    dim3 gg(LSEQ / BN, DM / BM, BB);
    gemm_kernel<<<gg, 256, smem_gemm>>>(bi, out);
}